// round 13
// baseline (speedup 1.0000x reference)
#include <cuda_runtime.h>
#include <cuda_fp16.h>
#include <math.h>
#include <stdint.h>

// ---------------- problem constants ----------------
constexpr int kB = 32;
constexpr int kC = 512;
constexpr int kHeads = 16;
constexpr int kSS = 4;
constexpr int kNW = 16;
constexpr int kL = 1024;
constexpr int kRows = kB * kL;    // 32768

// ---------------- scratch ----------------
__device__ __align__(16) float  g_ada[kB * 6 * kC];
__device__ __align__(16) __half g_hw[(size_t)kRows * kC];
__device__ __align__(16) __half g_qkv[(size_t)kRows * 3 * kC];
__device__ __align__(16) __half g_attn[(size_t)kRows * kC];
__device__ __align__(16) float  g_x2[(size_t)kRows * kC];
__device__ __align__(16) __half g_m[(size_t)kRows * kC];
__device__ __align__(16) __half g_fc1[(size_t)kRows * 4 * kC];
// FP16 weight copies
__device__ __align__(16) __half g_wq[1536 * 512];
__device__ __align__(16) __half g_wp[512 * 512];
__device__ __align__(16) __half g_w1[2048 * 512];
__device__ __align__(16) __half g_w2[512 * 2048];

__device__ __forceinline__ void cp16(uint32_t dst_smem, const void* src) {
    asm volatile("cp.async.cg.shared.global [%0], [%1], 16;" :: "r"(dst_smem), "l"(src));
}
__device__ __forceinline__ void mma_f16(float* c, uint32_t a0, uint32_t a1, uint32_t a2,
                                        uint32_t a3, uint32_t b0, uint32_t b1) {
    asm volatile(
        "mma.sync.aligned.m16n8k16.row.col.f32.f16.f16.f32 "
        "{%0,%1,%2,%3}, {%4,%5,%6,%7}, {%8,%9}, {%0,%1,%2,%3};"
        : "+f"(c[0]), "+f"(c[1]), "+f"(c[2]), "+f"(c[3])
        : "r"(a0), "r"(a1), "r"(a2), "r"(a3), "r"(b0), "r"(b1));
}
__device__ __forceinline__ void ldsm_x4(uint32_t& r0, uint32_t& r1, uint32_t& r2,
                                        uint32_t& r3, uint32_t addr) {
    asm volatile("ldmatrix.sync.aligned.m8n8.x4.shared.b16 {%0,%1,%2,%3}, [%4];"
                 : "=r"(r0), "=r"(r1), "=r"(r2), "=r"(r3) : "r"(addr));
}
__device__ __forceinline__ uint32_t ldsm_u32(const __half* p) {
    return *(const uint32_t*)p;
}

// Fast exact-GELU: A&S 7.1.26 erf (abs err <= 1.5e-7), MUFU rcp + MUFU exp.
__device__ __forceinline__ float gelu_fast(float x) {
    float z = fabsf(x) * 0.70710678118654752f;
    float t = __fdividef(1.f, 1.f + 0.3275911f * z);
    float poly = ((((1.061405429f * t - 1.453152027f) * t + 1.421413741f) * t
                   - 0.284496736f) * t + 0.254829592f) * t;
    float erfa = 1.f - poly * __expf(-z * z);
    float erfv = (x >= 0.f) ? erfa : -erfa;
    return 0.5f * x * (1.f + erfv);
}

// ---------------- fused setup: ada (blocks 0..31) + weight cvt (blocks 32..) ----
__global__ void setup_kernel(const float* __restrict__ cond,
                             const float* __restrict__ ada_w,
                             const float* __restrict__ ada_b,
                             const float* __restrict__ s0, __half* __restrict__ d0,
                             const float* __restrict__ s1, __half* __restrict__ d1,
                             const float* __restrict__ s2, __half* __restrict__ d2,
                             const float* __restrict__ s3, __half* __restrict__ d3) {
    if (blockIdx.x < 32) {
        int b = blockIdx.x;
        __shared__ float sc[kC];
        for (int i = threadIdx.x; i < kC; i += blockDim.x) {
            float c = cond[b * kC + i];
            sc[i] = c / (1.f + __expf(-c));
        }
        __syncthreads();
        for (int n = threadIdx.x; n < 6 * kC; n += blockDim.x) {
            const float* wr = ada_w + (size_t)n * kC;
            float acc = 0.f;
            #pragma unroll 8
            for (int k = 0; k < kC; ++k) acc += sc[k] * wr[k];
            g_ada[b * 6 * kC + n] = acc + ada_b[n];
        }
        return;
    }
    // weight convert: float4 ranges wq 196608, wp 65536, w1 262144, w2 262144
    int i = (blockIdx.x - 32) * blockDim.x + threadIdx.x;
    const float* s; __half* d;
    if (i < 196608)      { s = s0; d = d0; }
    else if (i < 262144) { s = s1; d = d1; i -= 196608; }
    else if (i < 524288) { s = s2; d = d2; i -= 262144; }
    else                 { s = s3; d = d3; i -= 524288; }
    float4 v = ((const float4*)s)[i];
    __half2* dp = (__half2*)(d + (size_t)i * 4);
    dp[0] = __float22half2_rn(make_float2(v.x, v.y));
    dp[1] = __float22half2_rn(make_float2(v.z, v.w));
}

// ---------------- LN + modulate (+ roll/partition gather); fp16 out ----------
__global__ void ln_mod_kernel(const float* __restrict__ x,
                              const float* __restrict__ lnw,
                              const float* __restrict__ lnb,
                              __half* __restrict__ out,
                              int mode, int sh_off, int sc_off) {
    int r = blockIdx.x;
    int b, src;
    if (mode == 0) {
        int win = r >> 6, t = r & 63;
        b = win >> 4;
        int nw_ = win & 15;
        int hb = nw_ >> 2, wb = nw_ & 3;
        int i = hb * 8 + (t >> 3), j = wb * 8 + (t & 7);
        int si = (i + kSS) & 31, sj = (j + kSS) & 31;
        src = b * kL + si * 32 + sj;
    } else {
        b = r >> 10;
        src = r;
    }
    int tid = threadIdx.x;
    float4 v = ((const float4*)(x + (size_t)src * kC))[tid];
    float s = v.x + v.y + v.z + v.w;
    float ss = v.x * v.x + v.y * v.y + v.z * v.z + v.w * v.w;
    #pragma unroll
    for (int o = 16; o; o >>= 1) {
        s  += __shfl_down_sync(0xffffffffu, s, o);
        ss += __shfl_down_sync(0xffffffffu, ss, o);
    }
    __shared__ float ps[4], pss[4], mv[2];
    int wp = tid >> 5;
    if ((tid & 31) == 0) { ps[wp] = s; pss[wp] = ss; }
    __syncthreads();
    if (tid == 0) {
        float S = ps[0] + ps[1] + ps[2] + ps[3];
        float S2 = pss[0] + pss[1] + pss[2] + pss[3];
        float mu = S / kC;
        float var = S2 / kC - mu * mu;
        mv[0] = mu;
        mv[1] = rsqrtf(var + 1e-5f);
    }
    __syncthreads();
    float mu = mv[0], rs = mv[1];
    int c0 = tid * 4;
    const float* sh = g_ada + b * 6 * kC + sh_off;
    const float* sc = g_ada + b * 6 * kC + sc_off;
    float vv[4] = {v.x, v.y, v.z, v.w};
    float o4[4];
    #pragma unroll
    for (int u = 0; u < 4; ++u) {
        float val = (vv[u] - mu) * rs * lnw[c0 + u] + lnb[c0 + u];
        o4[u] = val * (1.f + sc[c0 + u]) + sh[c0 + u];
    }
    __half2* op = (__half2*)(out + (size_t)r * kC + c0);
    op[0] = __float22half2_rn(make_float2(o4[0], o4[1]));
    op[1] = __float22half2_rn(make_float2(o4[2], o4[3]));
}

// ---------------- FP16 mma.sync NT GEMM, 2-stage cp.async, 128x64 block -------
// Warp tile 16x64, 8 warps (8M x 1N), K-tile 64 halves, smem stride 72 halves.
// 3 blocks/SM (register-lean: acc 32 regs/thread).
// epi&7: 0 bias. 1 bias+GELU. 2 res+gate*(bias+acc). 3 window-reverse + residual.
// epi&16: fp16 output.
constexpr int kKT = 64;
constexpr int kLSh = 72;
constexpr int kAStgH = 128 * kLSh;                 // A stage (halves)
constexpr int kBStgH = 64 * kLSh;                  // B stage (halves)
constexpr int kGemmSmem = 2 * (kAStgH + kBStgH) * 2;   // 55296 B

__global__ __launch_bounds__(256, 3) void gemm_f16(
        const __half* __restrict__ A, const __half* __restrict__ Bw,
        const float* __restrict__ bias, void* __restrict__ Cv,
        int M, int N, int K, int epi,
        const float* __restrict__ res, int gate_off) {
    extern __shared__ __half hsm[];
    __half* As = hsm;                       // [2][128][72]
    __half* Bs = hsm + 2 * kAStgH;          // [2][64][72]

    int tid = threadIdx.x;
    int lane = tid & 31;
    int warp = tid >> 5;
    int gid = lane >> 2;
    int tig = lane & 3;

    float acc[8][4];
    #pragma unroll
    for (int nt = 0; nt < 8; ++nt)
        #pragma unroll
        for (int i = 0; i < 4; ++i) acc[nt][i] = 0.f;

    const __half* Ag = A + (size_t)(blockIdx.y * 128) * K;
    const __half* Bg = Bw + (size_t)(blockIdx.x * 64) * K;

    uint32_t sA = (uint32_t)__cvta_generic_to_shared(As);
    uint32_t sB = (uint32_t)__cvta_generic_to_shared(Bs);

    int a_row = warp * 16 + (lane & 15);
    int a_c8  = (lane >> 4) * 8;
    int b_row = ((lane >> 4) & 1) * 8 + (lane & 7);
    int b_c8  = ((lane >> 3) & 1) * 8;

    auto load_tile = [&](int buf, int kt) {
        // A: 128 rows x 8 x16B chunks = 1024 chunks, 4/thread
        #pragma unroll
        for (int p = 0; p < 4; ++p) {
            int idx = tid + p * 256;
            int row = idx >> 3, c16 = idx & 7;
            uint32_t doff = (uint32_t)((buf * kAStgH + row * kLSh + c16 * 8) * 2);
            cp16(sA + doff, Ag + (size_t)row * K + kt + c16 * 8);
        }
        // B: 64 rows x 8 chunks = 512 chunks, 2/thread
        #pragma unroll
        for (int p = 0; p < 2; ++p) {
            int idx = tid + p * 256;
            int row = idx >> 3, c16 = idx & 7;
            uint32_t doff = (uint32_t)((buf * kBStgH + row * kLSh + c16 * 8) * 2);
            cp16(sB + doff, Bg + (size_t)row * K + kt + c16 * 8);
        }
        asm volatile("cp.async.commit_group;" ::: "memory");
    };

    const int T = K / kKT;
    load_tile(0, 0);

    for (int t = 0; t < T; ++t) {
        if (t + 1 < T) {
            load_tile((t + 1) & 1, (t + 1) * kKT);
            asm volatile("cp.async.wait_group 1;" ::: "memory");
        } else {
            asm volatile("cp.async.wait_group 0;" ::: "memory");
        }
        __syncthreads();

        uint32_t aStage = sA + (uint32_t)((t & 1) * kAStgH * 2);
        uint32_t bStage = sB + (uint32_t)((t & 1) * kBStgH * 2);

        #pragma unroll
        for (int kk = 0; kk < kKT; kk += 16) {
            uint32_t af[4];
            {
                uint32_t ad = aStage + (uint32_t)((a_row * kLSh + kk + a_c8) * 2);
                ldsm_x4(af[0], af[1], af[2], af[3], ad);
            }
            uint32_t bf[8][2];
            #pragma unroll
            for (int nt0 = 0; nt0 < 8; nt0 += 2) {
                uint32_t bd = bStage + (uint32_t)(((b_row + nt0 * 8) * kLSh + kk + b_c8) * 2);
                ldsm_x4(bf[nt0][0], bf[nt0][1], bf[nt0 + 1][0], bf[nt0 + 1][1], bd);
            }
            #pragma unroll
            for (int nt = 0; nt < 8; ++nt)
                mma_f16(acc[nt], af[0], af[1], af[2], af[3], bf[nt][0], bf[nt][1]);
        }
        __syncthreads();
    }

    int mode = epi & 7;
    bool out_half = (epi & 16) != 0;
    int rbase = blockIdx.y * 128 + warp * 16;
    int cbase = blockIdx.x * 64;
    #pragma unroll
    for (int half = 0; half < 2; ++half) {
        int r = rbase + gid + half * 8;
        int b = r >> 10;
        const float* gate = g_ada + b * 6 * kC + gate_off;
        int rout = r;
        if (mode == 3) {
            int win = r >> 6, t = r & 63;
            int nw_ = win & 15;
            int i2 = (nw_ >> 2) * 8 + (t >> 3);
            int j2 = (nw_ & 3) * 8 + (t & 7);
            int ii = (i2 + kSS) & 31, jj = (j2 + kSS) & 31;
            rout = b * kL + ii * 32 + jj;
        }
        #pragma unroll
        for (int nt = 0; nt < 8; ++nt) {
            int c = cbase + nt * 8 + tig * 2;
            float v0 = acc[nt][half * 2 + 0] + bias[c];
            float v1 = acc[nt][half * 2 + 1] + bias[c + 1];
            if (mode == 1) {
                v0 = gelu_fast(v0);
                v1 = gelu_fast(v1);
            } else if (mode >= 2) {
                v0 = res[(size_t)rout * kC + c]     + gate[c]     * v0;
                v1 = res[(size_t)rout * kC + c + 1] + gate[c + 1] * v1;
            }
            if (out_half) {
                *(__half2*)((__half*)Cv + (size_t)rout * N + c) =
                    __float22half2_rn(make_float2(v0, v1));
            } else {
                *(float2*)((float*)Cv + (size_t)rout * N + c) = make_float2(v0, v1);
            }
        }
    }
}

// ---------------- window attention via FP16 MMA ----------------
constexpr int kQSh = 40;
constexpr int kSSf = 68;
constexpr int kSHh = 72;
__global__ __launch_bounds__(128) void attn_kernel(const float* __restrict__ rpb) {
    int win = blockIdx.x, head = blockIdx.y;
    __shared__ __half qs[64 * kQSh];
    __shared__ __half ks[64 * kQSh];
    __shared__ __half vt[32 * kSHh];
    __shared__ __half sh[64 * kSHh];
    __shared__ float  s [64 * kSSf];
    __shared__ int sid[64];
    int tid = threadIdx.x;
    int lane = tid & 31;
    int warp = tid >> 5;
    int gid = lane >> 2;
    int tig = lane & 3;

    const __half* base = g_qkv + (size_t)win * 64 * 1536 + head * 32;
    #pragma unroll
    for (int p = 0; p < 2; ++p) {
        int idx = tid + p * 128;
        int n = idx >> 2, c8 = (idx & 3) * 8;
        *(uint4*)(qs + n * kQSh + c8) = *(const uint4*)(base + (size_t)n * 1536 + c8);
        *(uint4*)(ks + n * kQSh + c8) = *(const uint4*)(base + (size_t)n * 1536 + 512 + c8);
    }
    #pragma unroll
    for (int p = 0; p < 8; ++p) {
        int idx = tid + p * 128;
        int n = idx >> 4, d2 = (idx & 15) * 2;
        __half2 v = *(const __half2*)(base + (size_t)n * 1536 + 1024 + d2);
        vt[(d2    ) * kSHh + n] = __low2half(v);
        vt[(d2 + 1) * kSHh + n] = __high2half(v);
    }
    if (tid < 64) {
        int nw_ = win & 15, hb = nw_ >> 2, wb = nw_ & 3;
        int i = hb * 8 + (tid >> 3), j = wb * 8 + (tid & 7);
        int ri = i < 24 ? 0 : (i < 28 ? 1 : 2);
        int rj = j < 24 ? 0 : (j < 28 ? 1 : 2);
        sid[tid] = ri * 3 + rj;
    }
    __syncthreads();

    float c[8][4];
    #pragma unroll
    for (int nt = 0; nt < 8; ++nt)
        #pragma unroll
        for (int i = 0; i < 4; ++i) c[nt][i] = 0.f;

    int m0 = warp * 16 + gid;
    #pragma unroll
    for (int kk = 0; kk < 32; kk += 16) {
        uint32_t a0 = ldsm_u32(qs + (m0    ) * kQSh + kk + 2 * tig);
        uint32_t a1 = ldsm_u32(qs + (m0 + 8) * kQSh + kk + 2 * tig);
        uint32_t a2 = ldsm_u32(qs + (m0    ) * kQSh + kk + 2 * tig + 8);
        uint32_t a3 = ldsm_u32(qs + (m0 + 8) * kQSh + kk + 2 * tig + 8);
        #pragma unroll
        for (int nt = 0; nt < 8; ++nt) {
            int n0 = nt * 8 + gid;
            uint32_t b0 = ldsm_u32(ks + n0 * kQSh + kk + 2 * tig);
            uint32_t b1 = ldsm_u32(ks + n0 * kQSh + kk + 2 * tig + 8);
            mma_f16(c[nt], a0, a1, a2, a3, b0, b1);
        }
    }

    const float scale = 0.17677669529663687f;
    #pragma unroll
    for (int nt = 0; nt < 8; ++nt) {
        #pragma unroll
        for (int idx = 0; idx < 4; ++idx) {
            int row = warp * 16 + gid + ((idx >> 1) << 3);
            int col = nt * 8 + tig * 2 + (idx & 1);
            int di = (row >> 3) - (col >> 3) + 7;
            int dj = (row & 7) - (col & 7) + 7;
            float bias_ = rpb[(di * 15 + dj) * kHeads + head];
            float msk = (sid[row] != sid[col]) ? -100.f : 0.f;
            s[row * kSSf + col] = c[nt][idx] * scale + bias_ + msk;
        }
    }
    __syncthreads();

    if (tid < 64) {
        float* sr = s + tid * kSSf;
        float mx = -1e30f;
        #pragma unroll
        for (int m4 = 0; m4 < 16; ++m4) {
            float4 v = *(float4*)(sr + m4 * 4);
            mx = fmaxf(mx, fmaxf(fmaxf(v.x, v.y), fmaxf(v.z, v.w)));
        }
        float sum = 0.f;
        #pragma unroll
        for (int m4 = 0; m4 < 16; ++m4) {
            float4 v = *(float4*)(sr + m4 * 4);
            v.x = __expf(v.x - mx); v.y = __expf(v.y - mx);
            v.z = __expf(v.z - mx); v.w = __expf(v.w - mx);
            sum += v.x + v.y + v.z + v.w;
            *(float4*)(sr + m4 * 4) = v;
        }
        float inv = __fdividef(1.f, sum);
        __half2* shr = (__half2*)(sh + tid * kSHh);
        #pragma unroll
        for (int m4 = 0; m4 < 16; ++m4) {
            float4 v = *(float4*)(sr + m4 * 4);
            shr[m4 * 2 + 0] = __float22half2_rn(make_float2(v.x * inv, v.y * inv));
            shr[m4 * 2 + 1] = __float22half2_rn(make_float2(v.z * inv, v.w * inv));
        }
    }
    __syncthreads();

    float o[4][4];
    #pragma unroll
    for (int nt = 0; nt < 4; ++nt)
        #pragma unroll
        for (int i = 0; i < 4; ++i) o[nt][i] = 0.f;

    #pragma unroll
    for (int kk = 0; kk < 64; kk += 16) {
        uint32_t a0 = ldsm_u32(sh + (m0    ) * kSHh + kk + 2 * tig);
        uint32_t a1 = ldsm_u32(sh + (m0 + 8) * kSHh + kk + 2 * tig);
        uint32_t a2 = ldsm_u32(sh + (m0    ) * kSHh + kk + 2 * tig + 8);
        uint32_t a3 = ldsm_u32(sh + (m0 + 8) * kSHh + kk + 2 * tig + 8);
        #pragma unroll
        for (int nt = 0; nt < 4; ++nt) {
            int n0 = nt * 8 + gid;
            uint32_t b0 = ldsm_u32(vt + n0 * kSHh + kk + 2 * tig);
            uint32_t b1 = ldsm_u32(vt + n0 * kSHh + kk + 2 * tig + 8);
            mma_f16(o[nt], a0, a1, a2, a3, b0, b1);
        }
    }

    __half* outp = g_attn + (size_t)win * 64 * kC + head * 32;
    #pragma unroll
    for (int half = 0; half < 2; ++half) {
        int row = warp * 16 + gid + half * 8;
        #pragma unroll
        for (int nt = 0; nt < 4; ++nt) {
            int col = nt * 8 + tig * 2;
            *(__half2*)(outp + (size_t)row * kC + col) =
                __float22half2_rn(make_float2(o[nt][half * 2], o[nt][half * 2 + 1]));
        }
    }
}

// ---------------- launch ----------------
extern "C" void kernel_launch(void* const* d_in, const int* in_sizes, int n_in,
                              void* d_out, int out_size) {
    const float* x       = (const float*)d_in[0];
    const float* cond    = (const float*)d_in[1];
    const float* norm1_w = (const float*)d_in[2];
    const float* norm1_b = (const float*)d_in[3];
    const float* qkv_w   = (const float*)d_in[4];
    const float* qkv_b   = (const float*)d_in[5];
    const float* rpb     = (const float*)d_in[6];
    const float* proj_w  = (const float*)d_in[7];
    const float* proj_b  = (const float*)d_in[8];
    const float* norm2_w = (const float*)d_in[9];
    const float* norm2_b = (const float*)d_in[10];
    const float* fc1_w   = (const float*)d_in[11];
    const float* fc1_b   = (const float*)d_in[12];
    const float* fc2_w   = (const float*)d_in[13];
    const float* fc2_b   = (const float*)d_in[14];
    const float* ada_w   = (const float*)d_in[15];
    const float* ada_b   = (const float*)d_in[16];
    float* out = (float*)d_out;

    void *p_hw, *p_qkv, *p_attn, *p_x2, *p_m, *p_fc1;
    void *p_wq, *p_wp, *p_w1, *p_w2;
    cudaGetSymbolAddress(&p_hw,   g_hw);
    cudaGetSymbolAddress(&p_qkv,  g_qkv);
    cudaGetSymbolAddress(&p_attn, g_attn);
    cudaGetSymbolAddress(&p_x2,   g_x2);
    cudaGetSymbolAddress(&p_m,    g_m);
    cudaGetSymbolAddress(&p_fc1,  g_fc1);
    cudaGetSymbolAddress(&p_wq,   g_wq);
    cudaGetSymbolAddress(&p_wp,   g_wp);
    cudaGetSymbolAddress(&p_w1,   g_w1);
    cudaGetSymbolAddress(&p_w2,   g_w2);

    static bool attr_set = false;
    if (!attr_set) {
        cudaFuncSetAttribute(gemm_f16, cudaFuncAttributeMaxDynamicSharedMemorySize, kGemmSmem);
        attr_set = true;
    }

    // 1. setup: ada (32 blocks) + weight fp16 convert (3072 blocks)
    setup_kernel<<<32 + 786432 / 256, 256>>>(cond, ada_w, ada_b,
                                             qkv_w, (__half*)p_wq, proj_w, (__half*)p_wp,
                                             fc1_w, (__half*)p_w1, fc2_w, (__half*)p_w2);
    // 2. LN1 + modulate + roll + window partition -> g_hw (fp16)
    ln_mod_kernel<<<kRows, 128>>>(x, norm1_w, norm1_b, (__half*)p_hw, 0, 0, kC);
    // 3. qkv (fp16 out)
    gemm_f16<<<dim3(24, 256), 256, kGemmSmem>>>(
        (const __half*)p_hw, (const __half*)p_wq, qkv_b, p_qkv, kRows, 1536, 512, 0 | 16, nullptr, 0);
    // 4. windowed attention -> g_attn (fp16)
    attn_kernel<<<dim3(kB * kNW, kHeads), 128>>>(rpb);
    // 5. proj GEMM + window-reverse + MSA residual -> g_x2 (fp32)
    gemm_f16<<<dim3(8, 256), 256, kGemmSmem>>>(
        (const __half*)p_attn, (const __half*)p_wp, proj_b, p_x2, kRows, 512, 512, 3, x, 2 * kC);
    // 6. LN2 + modulate -> g_m (fp16)
    ln_mod_kernel<<<kRows, 128>>>((const float*)p_x2, norm2_w, norm2_b, (__half*)p_m,
                                  1, 3 * kC, 4 * kC);
    // 7. fc1 + GELU -> g_fc1 (fp16)
    gemm_f16<<<dim3(32, 256), 256, kGemmSmem>>>(
        (const __half*)p_m, (const __half*)p_w1, fc1_b, p_fc1, kRows, 2048, 512, 1 | 16, nullptr, 0);
    // 8. fc2 + gated residual -> d_out (fp32)
    gemm_f16<<<dim3(8, 256), 256, kGemmSmem>>>(
        (const __half*)p_fc1, (const __half*)p_w2, fc2_b, out, kRows, 512, 2048, 2, (const float*)p_x2, 5 * kC);
}

// round 14
// speedup vs baseline: 1.0933x; 1.0933x over previous
#include <cuda_runtime.h>
#include <cuda_fp16.h>
#include <math.h>
#include <stdint.h>

// ---------------- problem constants ----------------
constexpr int kB = 32;
constexpr int kC = 512;
constexpr int kHeads = 16;
constexpr int kSS = 4;
constexpr int kNW = 16;
constexpr int kL = 1024;
constexpr int kRows = kB * kL;    // 32768

// ---------------- scratch ----------------
__device__ __align__(16) float  g_ada[kB * 6 * kC];
__device__ __align__(16) __half g_hw[(size_t)kRows * kC];
__device__ __align__(16) __half g_qkv[(size_t)kRows * 3 * kC];
__device__ __align__(16) __half g_attn[(size_t)kRows * kC];
__device__ __align__(16) float  g_x2[(size_t)kRows * kC];
__device__ __align__(16) __half g_m[(size_t)kRows * kC];
__device__ __align__(16) __half g_fc1[(size_t)kRows * 4 * kC];
// FP16 weight copies
__device__ __align__(16) __half g_wq[1536 * 512];
__device__ __align__(16) __half g_wp[512 * 512];
__device__ __align__(16) __half g_w1[2048 * 512];
__device__ __align__(16) __half g_w2[512 * 2048];

__device__ __forceinline__ void cp16(uint32_t dst_smem, const void* src) {
    asm volatile("cp.async.cg.shared.global [%0], [%1], 16;" :: "r"(dst_smem), "l"(src));
}
__device__ __forceinline__ void mma_f16(float* c, uint32_t a0, uint32_t a1, uint32_t a2,
                                        uint32_t a3, uint32_t b0, uint32_t b1) {
    asm volatile(
        "mma.sync.aligned.m16n8k16.row.col.f32.f16.f16.f32 "
        "{%0,%1,%2,%3}, {%4,%5,%6,%7}, {%8,%9}, {%0,%1,%2,%3};"
        : "+f"(c[0]), "+f"(c[1]), "+f"(c[2]), "+f"(c[3])
        : "r"(a0), "r"(a1), "r"(a2), "r"(a3), "r"(b0), "r"(b1));
}
__device__ __forceinline__ void ldsm_x4(uint32_t& r0, uint32_t& r1, uint32_t& r2,
                                        uint32_t& r3, uint32_t addr) {
    asm volatile("ldmatrix.sync.aligned.m8n8.x4.shared.b16 {%0,%1,%2,%3}, [%4];"
                 : "=r"(r0), "=r"(r1), "=r"(r2), "=r"(r3) : "r"(addr));
}
__device__ __forceinline__ uint32_t ldsm_u32(const __half* p) {
    return *(const uint32_t*)p;
}

// Fast exact-GELU: A&S 7.1.26 erf (abs err <= 1.5e-7), MUFU rcp + MUFU exp.
__device__ __forceinline__ float gelu_fast(float x) {
    float z = fabsf(x) * 0.70710678118654752f;
    float t = __fdividef(1.f, 1.f + 0.3275911f * z);
    float poly = ((((1.061405429f * t - 1.453152027f) * t + 1.421413741f) * t
                   - 0.284496736f) * t + 0.254829592f) * t;
    float erfa = 1.f - poly * __expf(-z * z);
    float erfv = (x >= 0.f) ? erfa : -erfa;
    return 0.5f * x * (1.f + erfv);
}

// ---------------- fused setup: ada (blocks 0..31) + weight cvt (blocks 32..) ----
__global__ void setup_kernel(const float* __restrict__ cond,
                             const float* __restrict__ ada_w,
                             const float* __restrict__ ada_b,
                             const float* __restrict__ s0, __half* __restrict__ d0,
                             const float* __restrict__ s1, __half* __restrict__ d1,
                             const float* __restrict__ s2, __half* __restrict__ d2,
                             const float* __restrict__ s3, __half* __restrict__ d3) {
    if (blockIdx.x < 32) {
        int b = blockIdx.x;
        __shared__ float sc[kC];
        for (int i = threadIdx.x; i < kC; i += blockDim.x) {
            float c = cond[b * kC + i];
            sc[i] = c / (1.f + __expf(-c));
        }
        __syncthreads();
        for (int n = threadIdx.x; n < 6 * kC; n += blockDim.x) {
            const float* wr = ada_w + (size_t)n * kC;
            float acc = 0.f;
            #pragma unroll 8
            for (int k = 0; k < kC; ++k) acc += sc[k] * wr[k];
            g_ada[b * 6 * kC + n] = acc + ada_b[n];
        }
        return;
    }
    int i = (blockIdx.x - 32) * blockDim.x + threadIdx.x;
    const float* s; __half* d;
    if (i < 196608)      { s = s0; d = d0; }
    else if (i < 262144) { s = s1; d = d1; i -= 196608; }
    else if (i < 524288) { s = s2; d = d2; i -= 262144; }
    else                 { s = s3; d = d3; i -= 524288; }
    float4 v = ((const float4*)s)[i];
    __half2* dp = (__half2*)(d + (size_t)i * 4);
    dp[0] = __float22half2_rn(make_float2(v.x, v.y));
    dp[1] = __float22half2_rn(make_float2(v.z, v.w));
}

// ---------------- LN + modulate (+ roll/partition gather); fp16 out ----------
__global__ void ln_mod_kernel(const float* __restrict__ x,
                              const float* __restrict__ lnw,
                              const float* __restrict__ lnb,
                              __half* __restrict__ out,
                              int mode, int sh_off, int sc_off) {
    int r = blockIdx.x;
    int b, src;
    if (mode == 0) {
        int win = r >> 6, t = r & 63;
        b = win >> 4;
        int nw_ = win & 15;
        int hb = nw_ >> 2, wb = nw_ & 3;
        int i = hb * 8 + (t >> 3), j = wb * 8 + (t & 7);
        int si = (i + kSS) & 31, sj = (j + kSS) & 31;
        src = b * kL + si * 32 + sj;
    } else {
        b = r >> 10;
        src = r;
    }
    int tid = threadIdx.x;
    float4 v = ((const float4*)(x + (size_t)src * kC))[tid];
    float s = v.x + v.y + v.z + v.w;
    float ss = v.x * v.x + v.y * v.y + v.z * v.z + v.w * v.w;
    #pragma unroll
    for (int o = 16; o; o >>= 1) {
        s  += __shfl_down_sync(0xffffffffu, s, o);
        ss += __shfl_down_sync(0xffffffffu, ss, o);
    }
    __shared__ float ps[4], pss[4], mv[2];
    int wp = tid >> 5;
    if ((tid & 31) == 0) { ps[wp] = s; pss[wp] = ss; }
    __syncthreads();
    if (tid == 0) {
        float S = ps[0] + ps[1] + ps[2] + ps[3];
        float S2 = pss[0] + pss[1] + pss[2] + pss[3];
        float mu = S / kC;
        float var = S2 / kC - mu * mu;
        mv[0] = mu;
        mv[1] = rsqrtf(var + 1e-5f);
    }
    __syncthreads();
    float mu = mv[0], rs = mv[1];
    int c0 = tid * 4;
    const float* sh = g_ada + b * 6 * kC + sh_off;
    const float* sc = g_ada + b * 6 * kC + sc_off;
    float vv[4] = {v.x, v.y, v.z, v.w};
    float o4[4];
    #pragma unroll
    for (int u = 0; u < 4; ++u) {
        float val = (vv[u] - mu) * rs * lnw[c0 + u] + lnb[c0 + u];
        o4[u] = val * (1.f + sc[c0 + u]) + sh[c0 + u];
    }
    __half2* op = (__half2*)(out + (size_t)r * kC + c0);
    op[0] = __float22half2_rn(make_float2(o4[0], o4[1]));
    op[1] = __float22half2_rn(make_float2(o4[2], o4[3]));
}

// ---------------- FP16 mma.sync NT GEMM, 2-stage cp.async, 128x128 block ------
// Warp tile 32x64, 8 warps (4M x 2N), K-tile 64 halves, smem stride 72 halves.
// epi&7: 0 bias. 1 bias+GELU. 2 res+gate*(bias+acc). 3 window-reverse + residual.
// epi&16: fp16 output.
constexpr int kKT = 64;
constexpr int kLSh = 72;
constexpr int kStgH = 128 * kLSh;
constexpr int kGemmSmem = 4 * kStgH * 2;   // 73728 B

__global__ __launch_bounds__(256, 2) void gemm_f16(
        const __half* __restrict__ A, const __half* __restrict__ Bw,
        const float* __restrict__ bias, void* __restrict__ Cv,
        int M, int N, int K, int epi,
        const float* __restrict__ res, int gate_off) {
    extern __shared__ __half hsm[];
    __half* As = hsm;                    // [2][128][72]
    __half* Bs = hsm + 2 * kStgH;        // [2][128][72]

    int tid = threadIdx.x;
    int lane = tid & 31;
    int warp = tid >> 5;
    int warp_m = warp & 3;
    int warp_n = warp >> 2;
    int gid = lane >> 2;
    int tig = lane & 3;

    float acc[2][8][4];
    #pragma unroll
    for (int mt = 0; mt < 2; ++mt)
        #pragma unroll
        for (int nt = 0; nt < 8; ++nt)
            #pragma unroll
            for (int i = 0; i < 4; ++i) acc[mt][nt][i] = 0.f;

    const __half* Ag = A + (size_t)(blockIdx.y * 128) * K;
    const __half* Bg = Bw + (size_t)(blockIdx.x * 128) * K;

    uint32_t sA = (uint32_t)__cvta_generic_to_shared(As);
    uint32_t sB = (uint32_t)__cvta_generic_to_shared(Bs);

    int a_row = warp_m * 32 + (lane & 15);
    int a_c8  = (lane >> 4) * 8;
    int b_row = warp_n * 64 + ((lane >> 4) & 1) * 8 + (lane & 7);
    int b_c8  = ((lane >> 3) & 1) * 8;

    auto load_tile = [&](int buf, int kt) {
        #pragma unroll
        for (int p = 0; p < 4; ++p) {
            int idx = tid + p * 256;
            int row = idx >> 3, c16 = idx & 7;
            uint32_t doff = (uint32_t)((buf * kStgH + row * kLSh + c16 * 8) * 2);
            cp16(sA + doff, Ag + (size_t)row * K + kt + c16 * 8);
            cp16(sB + doff, Bg + (size_t)row * K + kt + c16 * 8);
        }
        asm volatile("cp.async.commit_group;" ::: "memory");
    };

    const int T = K / kKT;
    load_tile(0, 0);

    for (int t = 0; t < T; ++t) {
        if (t + 1 < T) {
            load_tile((t + 1) & 1, (t + 1) * kKT);
            asm volatile("cp.async.wait_group 1;" ::: "memory");
        } else {
            asm volatile("cp.async.wait_group 0;" ::: "memory");
        }
        __syncthreads();

        uint32_t aStage = sA + (uint32_t)((t & 1) * kStgH * 2);
        uint32_t bStage = sB + (uint32_t)((t & 1) * kStgH * 2);

        #pragma unroll
        for (int kk = 0; kk < kKT; kk += 16) {
            uint32_t af[2][4];
            #pragma unroll
            for (int mt = 0; mt < 2; ++mt) {
                uint32_t ad = aStage + (uint32_t)(((a_row + mt * 16) * kLSh + kk + a_c8) * 2);
                ldsm_x4(af[mt][0], af[mt][1], af[mt][2], af[mt][3], ad);
            }
            uint32_t bf[8][2];
            #pragma unroll
            for (int nt0 = 0; nt0 < 8; nt0 += 2) {
                uint32_t bd = bStage + (uint32_t)(((b_row + nt0 * 8) * kLSh + kk + b_c8) * 2);
                ldsm_x4(bf[nt0][0], bf[nt0][1], bf[nt0 + 1][0], bf[nt0 + 1][1], bd);
            }
            #pragma unroll
            for (int nt = 0; nt < 8; ++nt)
                #pragma unroll
                for (int mt = 0; mt < 2; ++mt)
                    mma_f16(acc[mt][nt], af[mt][0], af[mt][1], af[mt][2], af[mt][3],
                            bf[nt][0], bf[nt][1]);
        }
        __syncthreads();
    }

    int mode = epi & 7;
    bool out_half = (epi & 16) != 0;
    int rbase = blockIdx.y * 128 + warp_m * 32;
    int cbase = blockIdx.x * 128 + warp_n * 64;
    #pragma unroll
    for (int mt = 0; mt < 2; ++mt) {
        #pragma unroll
        for (int half = 0; half < 2; ++half) {
            int r = rbase + mt * 16 + gid + half * 8;
            int b = r >> 10;
            const float* gate = g_ada + b * 6 * kC + gate_off;
            int rout = r;
            if (mode == 3) {
                int win = r >> 6, t = r & 63;
                int nw_ = win & 15;
                int i2 = (nw_ >> 2) * 8 + (t >> 3);
                int j2 = (nw_ & 3) * 8 + (t & 7);
                int ii = (i2 + kSS) & 31, jj = (j2 + kSS) & 31;
                rout = b * kL + ii * 32 + jj;
            }
            #pragma unroll
            for (int nt = 0; nt < 8; ++nt) {
                int c = cbase + nt * 8 + tig * 2;
                float v0 = acc[mt][nt][half * 2 + 0] + bias[c];
                float v1 = acc[mt][nt][half * 2 + 1] + bias[c + 1];
                if (mode == 1) {
                    v0 = gelu_fast(v0);
                    v1 = gelu_fast(v1);
                } else if (mode >= 2) {
                    v0 = res[(size_t)rout * kC + c]     + gate[c]     * v0;
                    v1 = res[(size_t)rout * kC + c + 1] + gate[c + 1] * v1;
                }
                if (out_half) {
                    *(__half2*)((__half*)Cv + (size_t)rout * N + c) =
                        __float22half2_rn(make_float2(v0, v1));
                } else {
                    *(float2*)((float*)Cv + (size_t)rout * N + c) = make_float2(v0, v1);
                }
            }
        }
    }
}

// ---------------- window attention via FP16 MMA, register softmax ------------
constexpr int kQSh = 40;
constexpr int kSHh = 72;
__global__ __launch_bounds__(128) void attn_kernel(const float* __restrict__ rpb) {
    int win = blockIdx.x, head = blockIdx.y;
    __shared__ __half qs[64 * kQSh];
    __shared__ __half ks[64 * kQSh];
    __shared__ __half vt[32 * kSHh];
    __shared__ __half sh[64 * kSHh];
    __shared__ int sid[64];
    int tid = threadIdx.x;
    int lane = tid & 31;
    int warp = tid >> 5;
    int gid = lane >> 2;
    int tig = lane & 3;

    const __half* base = g_qkv + (size_t)win * 64 * 1536 + head * 32;
    #pragma unroll
    for (int p = 0; p < 2; ++p) {
        int idx = tid + p * 128;
        int n = idx >> 2, c8 = (idx & 3) * 8;
        *(uint4*)(qs + n * kQSh + c8) = *(const uint4*)(base + (size_t)n * 1536 + c8);
        *(uint4*)(ks + n * kQSh + c8) = *(const uint4*)(base + (size_t)n * 1536 + 512 + c8);
    }
    #pragma unroll
    for (int p = 0; p < 8; ++p) {
        int idx = tid + p * 128;
        int n = idx >> 4, d2 = (idx & 15) * 2;
        __half2 v = *(const __half2*)(base + (size_t)n * 1536 + 1024 + d2);
        vt[(d2    ) * kSHh + n] = __low2half(v);
        vt[(d2 + 1) * kSHh + n] = __high2half(v);
    }
    if (tid < 64) {
        int nw_ = win & 15, hb = nw_ >> 2, wb = nw_ & 3;
        int i = hb * 8 + (tid >> 3), j = wb * 8 + (tid & 7);
        int ri = i < 24 ? 0 : (i < 28 ? 1 : 2);
        int rj = j < 24 ? 0 : (j < 28 ? 1 : 2);
        sid[tid] = ri * 3 + rj;
    }
    __syncthreads();

    // ---- S = Q K^T ----
    float c[8][4];
    #pragma unroll
    for (int nt = 0; nt < 8; ++nt)
        #pragma unroll
        for (int i = 0; i < 4; ++i) c[nt][i] = 0.f;

    int m0 = warp * 16 + gid;
    #pragma unroll
    for (int kk = 0; kk < 32; kk += 16) {
        uint32_t a0 = ldsm_u32(qs + (m0    ) * kQSh + kk + 2 * tig);
        uint32_t a1 = ldsm_u32(qs + (m0 + 8) * kQSh + kk + 2 * tig);
        uint32_t a2 = ldsm_u32(qs + (m0    ) * kQSh + kk + 2 * tig + 8);
        uint32_t a3 = ldsm_u32(qs + (m0 + 8) * kQSh + kk + 2 * tig + 8);
        #pragma unroll
        for (int nt = 0; nt < 8; ++nt) {
            int n0 = nt * 8 + gid;
            uint32_t b0 = ldsm_u32(ks + n0 * kQSh + kk + 2 * tig);
            uint32_t b1 = ldsm_u32(ks + n0 * kQSh + kk + 2 * tig + 8);
            mma_f16(c[nt], a0, a1, a2, a3, b0, b1);
        }
    }

    // scale + rel-pos bias + shift mask, in registers
    const float scale = 0.17677669529663687f;
    #pragma unroll
    for (int nt = 0; nt < 8; ++nt) {
        #pragma unroll
        for (int idx = 0; idx < 4; ++idx) {
            int row = m0 + ((idx >> 1) << 3);
            int col = nt * 8 + tig * 2 + (idx & 1);
            int di = (row >> 3) - (col >> 3) + 7;
            int dj = (row & 7) - (col & 7) + 7;
            float bias_ = rpb[(di * 15 + dj) * kHeads + head];
            float msk = (sid[row] != sid[col]) ? -100.f : 0.f;
            c[nt][idx] = c[nt][idx] * scale + bias_ + msk;
        }
    }

    // ---- register softmax: rows m0 (idx half 0) and m0+8 (half 1) ----
    #pragma unroll
    for (int half = 0; half < 2; ++half) {
        int row = m0 + half * 8;
        float mx = -1e30f;
        #pragma unroll
        for (int nt = 0; nt < 8; ++nt)
            mx = fmaxf(mx, fmaxf(c[nt][half * 2], c[nt][half * 2 + 1]));
        mx = fmaxf(mx, __shfl_xor_sync(0xffffffffu, mx, 1));
        mx = fmaxf(mx, __shfl_xor_sync(0xffffffffu, mx, 2));
        float sum = 0.f;
        #pragma unroll
        for (int nt = 0; nt < 8; ++nt) {
            float e0 = __expf(c[nt][half * 2    ] - mx);
            float e1 = __expf(c[nt][half * 2 + 1] - mx);
            c[nt][half * 2] = e0;
            c[nt][half * 2 + 1] = e1;
            sum += e0 + e1;
        }
        sum += __shfl_xor_sync(0xffffffffu, sum, 1);
        sum += __shfl_xor_sync(0xffffffffu, sum, 2);
        float inv = __fdividef(1.f, sum);
        #pragma unroll
        for (int nt = 0; nt < 8; ++nt) {
            int col = nt * 8 + tig * 2;
            *(__half2*)(sh + row * kSHh + col) =
                __float22half2_rn(make_float2(c[nt][half * 2] * inv,
                                              c[nt][half * 2 + 1] * inv));
        }
    }
    __syncwarp();   // S.V consumes only this warp's own rows of sh

    // ---- O = S V ----
    float o[4][4];
    #pragma unroll
    for (int nt = 0; nt < 4; ++nt)
        #pragma unroll
        for (int i = 0; i < 4; ++i) o[nt][i] = 0.f;

    #pragma unroll
    for (int kk = 0; kk < 64; kk += 16) {
        uint32_t a0 = ldsm_u32(sh + (m0    ) * kSHh + kk + 2 * tig);
        uint32_t a1 = ldsm_u32(sh + (m0 + 8) * kSHh + kk + 2 * tig);
        uint32_t a2 = ldsm_u32(sh + (m0    ) * kSHh + kk + 2 * tig + 8);
        uint32_t a3 = ldsm_u32(sh + (m0 + 8) * kSHh + kk + 2 * tig + 8);
        #pragma unroll
        for (int nt = 0; nt < 4; ++nt) {
            int n0 = nt * 8 + gid;
            uint32_t b0 = ldsm_u32(vt + n0 * kSHh + kk + 2 * tig);
            uint32_t b1 = ldsm_u32(vt + n0 * kSHh + kk + 2 * tig + 8);
            mma_f16(o[nt], a0, a1, a2, a3, b0, b1);
        }
    }

    __half* outp = g_attn + (size_t)win * 64 * kC + head * 32;
    #pragma unroll
    for (int half = 0; half < 2; ++half) {
        int row = m0 + half * 8;
        #pragma unroll
        for (int nt = 0; nt < 4; ++nt) {
            int col = nt * 8 + tig * 2;
            *(__half2*)(outp + (size_t)row * kC + col) =
                __float22half2_rn(make_float2(o[nt][half * 2], o[nt][half * 2 + 1]));
        }
    }
}

// ---------------- launch ----------------
extern "C" void kernel_launch(void* const* d_in, const int* in_sizes, int n_in,
                              void* d_out, int out_size) {
    const float* x       = (const float*)d_in[0];
    const float* cond    = (const float*)d_in[1];
    const float* norm1_w = (const float*)d_in[2];
    const float* norm1_b = (const float*)d_in[3];
    const float* qkv_w   = (const float*)d_in[4];
    const float* qkv_b   = (const float*)d_in[5];
    const float* rpb     = (const float*)d_in[6];
    const float* proj_w  = (const float*)d_in[7];
    const float* proj_b  = (const float*)d_in[8];
    const float* norm2_w = (const float*)d_in[9];
    const float* norm2_b = (const float*)d_in[10];
    const float* fc1_w   = (const float*)d_in[11];
    const float* fc1_b   = (const float*)d_in[12];
    const float* fc2_w   = (const float*)d_in[13];
    const float* fc2_b   = (const float*)d_in[14];
    const float* ada_w   = (const float*)d_in[15];
    const float* ada_b   = (const float*)d_in[16];
    float* out = (float*)d_out;

    void *p_hw, *p_qkv, *p_attn, *p_x2, *p_m, *p_fc1;
    void *p_wq, *p_wp, *p_w1, *p_w2;
    cudaGetSymbolAddress(&p_hw,   g_hw);
    cudaGetSymbolAddress(&p_qkv,  g_qkv);
    cudaGetSymbolAddress(&p_attn, g_attn);
    cudaGetSymbolAddress(&p_x2,   g_x2);
    cudaGetSymbolAddress(&p_m,    g_m);
    cudaGetSymbolAddress(&p_fc1,  g_fc1);
    cudaGetSymbolAddress(&p_wq,   g_wq);
    cudaGetSymbolAddress(&p_wp,   g_wp);
    cudaGetSymbolAddress(&p_w1,   g_w1);
    cudaGetSymbolAddress(&p_w2,   g_w2);

    static bool attr_set = false;
    if (!attr_set) {
        cudaFuncSetAttribute(gemm_f16, cudaFuncAttributeMaxDynamicSharedMemorySize, kGemmSmem);
        attr_set = true;
    }

    // 1. setup: ada (32 blocks) + weight fp16 convert (3072 blocks)
    setup_kernel<<<32 + 786432 / 256, 256>>>(cond, ada_w, ada_b,
                                             qkv_w, (__half*)p_wq, proj_w, (__half*)p_wp,
                                             fc1_w, (__half*)p_w1, fc2_w, (__half*)p_w2);
    // 2. LN1 + modulate + roll + window partition -> g_hw (fp16)
    ln_mod_kernel<<<kRows, 128>>>(x, norm1_w, norm1_b, (__half*)p_hw, 0, 0, kC);
    // 3. qkv (fp16 out)
    gemm_f16<<<dim3(12, 256), 256, kGemmSmem>>>(
        (const __half*)p_hw, (const __half*)p_wq, qkv_b, p_qkv, kRows, 1536, 512, 0 | 16, nullptr, 0);
    // 4. windowed attention -> g_attn (fp16)
    attn_kernel<<<dim3(kB * kNW, kHeads), 128>>>(rpb);
    // 5. proj GEMM + window-reverse + MSA residual -> g_x2 (fp32)
    gemm_f16<<<dim3(4, 256), 256, kGemmSmem>>>(
        (const __half*)p_attn, (const __half*)p_wp, proj_b, p_x2, kRows, 512, 512, 3, x, 2 * kC);
    // 6. LN2 + modulate -> g_m (fp16)
    ln_mod_kernel<<<kRows, 128>>>((const float*)p_x2, norm2_w, norm2_b, (__half*)p_m,
                                  1, 3 * kC, 4 * kC);
    // 7. fc1 + GELU -> g_fc1 (fp16)
    gemm_f16<<<dim3(16, 256), 256, kGemmSmem>>>(
        (const __half*)p_m, (const __half*)p_w1, fc1_b, p_fc1, kRows, 2048, 512, 1 | 16, nullptr, 0);
    // 8. fc2 + gated residual -> d_out (fp32)
    gemm_f16<<<dim3(4, 256), 256, kGemmSmem>>>(
        (const __half*)p_fc1, (const __half*)p_w2, fc2_b, out, kRows, 512, 2048, 2, (const float*)p_x2, 5 * kC);
}

// round 16
// speedup vs baseline: 1.1014x; 1.0075x over previous
#include <cuda_runtime.h>
#include <cuda_fp16.h>
#include <math.h>
#include <stdint.h>

// ---------------- problem constants ----------------
constexpr int kB = 32;
constexpr int kC = 512;
constexpr int kHeads = 16;
constexpr int kSS = 4;
constexpr int kNW = 16;
constexpr int kL = 1024;
constexpr int kRows = kB * kL;    // 32768

// ---------------- scratch ----------------
__device__ __align__(16) float  g_ada[kB * 6 * kC];
__device__ __align__(16) __half g_hw[(size_t)kRows * kC];
__device__ __align__(16) __half g_qkv[(size_t)kRows * 3 * kC];   // head-blocked layout
__device__ __align__(16) __half g_attn[(size_t)kRows * kC];
__device__ __align__(16) float  g_x2[(size_t)kRows * kC];
__device__ __align__(16) __half g_m[(size_t)kRows * kC];
__device__ __align__(16) __half g_fc1[(size_t)kRows * 4 * kC];
// FP16 weight copies
__device__ __align__(16) __half g_wq[1536 * 512];
__device__ __align__(16) __half g_wp[512 * 512];
__device__ __align__(16) __half g_w1[2048 * 512];
__device__ __align__(16) __half g_w2[512 * 2048];

__device__ __forceinline__ void cp16(uint32_t dst_smem, const void* src) {
    asm volatile("cp.async.cg.shared.global [%0], [%1], 16;" :: "r"(dst_smem), "l"(src));
}
__device__ __forceinline__ void mma_f16(float* c, uint32_t a0, uint32_t a1, uint32_t a2,
                                        uint32_t a3, uint32_t b0, uint32_t b1) {
    asm volatile(
        "mma.sync.aligned.m16n8k16.row.col.f32.f16.f16.f32 "
        "{%0,%1,%2,%3}, {%4,%5,%6,%7}, {%8,%9}, {%0,%1,%2,%3};"
        : "+f"(c[0]), "+f"(c[1]), "+f"(c[2]), "+f"(c[3])
        : "r"(a0), "r"(a1), "r"(a2), "r"(a3), "r"(b0), "r"(b1));
}
__device__ __forceinline__ void ldsm_x4(uint32_t& r0, uint32_t& r1, uint32_t& r2,
                                        uint32_t& r3, uint32_t addr) {
    asm volatile("ldmatrix.sync.aligned.m8n8.x4.shared.b16 {%0,%1,%2,%3}, [%4];"
                 : "=r"(r0), "=r"(r1), "=r"(r2), "=r"(r3) : "r"(addr));
}
__device__ __forceinline__ uint32_t ldsm_u32(const __half* p) {
    return *(const uint32_t*)p;
}

// Fast exact-GELU: A&S 7.1.26 erf (abs err <= 1.5e-7), MUFU rcp + MUFU exp.
__device__ __forceinline__ float gelu_fast(float x) {
    float z = fabsf(x) * 0.70710678118654752f;
    float t = __fdividef(1.f, 1.f + 0.3275911f * z);
    float poly = ((((1.061405429f * t - 1.453152027f) * t + 1.421413741f) * t
                   - 0.284496736f) * t + 0.254829592f) * t;
    float erfa = 1.f - poly * __expf(-z * z);
    float erfv = (x >= 0.f) ? erfa : -erfa;
    return 0.5f * x * (1.f + erfv);
}

// ---------------- fused setup: ada (blocks 0..31) + weight cvt (blocks 32..) ----
__global__ void setup_kernel(const float* __restrict__ cond,
                             const float* __restrict__ ada_w,
                             const float* __restrict__ ada_b,
                             const float* __restrict__ s0, __half* __restrict__ d0,
                             const float* __restrict__ s1, __half* __restrict__ d1,
                             const float* __restrict__ s2, __half* __restrict__ d2,
                             const float* __restrict__ s3, __half* __restrict__ d3) {
    if (blockIdx.x < 32) {
        int b = blockIdx.x;
        __shared__ float sc[kC];
        for (int i = threadIdx.x; i < kC; i += blockDim.x) {
            float c = cond[b * kC + i];
            sc[i] = c / (1.f + __expf(-c));
        }
        __syncthreads();
        for (int n = threadIdx.x; n < 6 * kC; n += blockDim.x) {
            const float* wr = ada_w + (size_t)n * kC;
            float acc = 0.f;
            #pragma unroll 8
            for (int k = 0; k < kC; ++k) acc += sc[k] * wr[k];
            g_ada[b * 6 * kC + n] = acc + ada_b[n];
        }
        return;
    }
    int i = (blockIdx.x - 32) * blockDim.x + threadIdx.x;
    const float* s; __half* d;
    if (i < 196608)      { s = s0; d = d0; }
    else if (i < 262144) { s = s1; d = d1; i -= 196608; }
    else if (i < 524288) { s = s2; d = d2; i -= 262144; }
    else                 { s = s3; d = d3; i -= 524288; }
    float4 v = ((const float4*)s)[i];
    __half2* dp = (__half2*)(d + (size_t)i * 4);
    dp[0] = __float22half2_rn(make_float2(v.x, v.y));
    dp[1] = __float22half2_rn(make_float2(v.z, v.w));
}

// ---------------- LN + modulate (+ roll/partition gather); fp16 out ----------
__global__ void ln_mod_kernel(const float* __restrict__ x,
                              const float* __restrict__ lnw,
                              const float* __restrict__ lnb,
                              __half* __restrict__ out,
                              int mode, int sh_off, int sc_off) {
    int r = blockIdx.x;
    int b, src;
    if (mode == 0) {
        int win = r >> 6, t = r & 63;
        b = win >> 4;
        int nw_ = win & 15;
        int hb = nw_ >> 2, wb = nw_ & 3;
        int i = hb * 8 + (t >> 3), j = wb * 8 + (t & 7);
        int si = (i + kSS) & 31, sj = (j + kSS) & 31;
        src = b * kL + si * 32 + sj;
    } else {
        b = r >> 10;
        src = r;
    }
    int tid = threadIdx.x;
    float4 v = ((const float4*)(x + (size_t)src * kC))[tid];
    float s = v.x + v.y + v.z + v.w;
    float ss = v.x * v.x + v.y * v.y + v.z * v.z + v.w * v.w;
    #pragma unroll
    for (int o = 16; o; o >>= 1) {
        s  += __shfl_down_sync(0xffffffffu, s, o);
        ss += __shfl_down_sync(0xffffffffu, ss, o);
    }
    __shared__ float ps[4], pss[4], mv[2];
    int wp = tid >> 5;
    if ((tid & 31) == 0) { ps[wp] = s; pss[wp] = ss; }
    __syncthreads();
    if (tid == 0) {
        float S = ps[0] + ps[1] + ps[2] + ps[3];
        float S2 = pss[0] + pss[1] + pss[2] + pss[3];
        float mu = S / kC;
        float var = S2 / kC - mu * mu;
        mv[0] = mu;
        mv[1] = rsqrtf(var + 1e-5f);
    }
    __syncthreads();
    float mu = mv[0], rs = mv[1];
    int c0 = tid * 4;
    const float* sh = g_ada + b * 6 * kC + sh_off;
    const float* sc = g_ada + b * 6 * kC + sc_off;
    float vv[4] = {v.x, v.y, v.z, v.w};
    float o4[4];
    #pragma unroll
    for (int u = 0; u < 4; ++u) {
        float val = (vv[u] - mu) * rs * lnw[c0 + u] + lnb[c0 + u];
        o4[u] = val * (1.f + sc[c0 + u]) + sh[c0 + u];
    }
    __half2* op = (__half2*)(out + (size_t)r * kC + c0);
    op[0] = __float22half2_rn(make_float2(o4[0], o4[1]));
    op[1] = __float22half2_rn(make_float2(o4[2], o4[3]));
}

// ---------------- FP16 mma.sync NT GEMM, 2-stage cp.async, 128x128 block ------
// Warp tile 32x64, 8 warps (4M x 2N), K-tile 64 halves, smem stride 72 halves.
// epi&7: 0 bias. 1 bias+GELU. 2 res+gate*(bias+acc). 3 window-reverse + residual.
// epi&16: fp16 output.  epi&32: head-blocked qkv output remap.
constexpr int kKT = 64;
constexpr int kLSh = 72;
constexpr int kStgH = 128 * kLSh;
constexpr int kGemmSmem = 4 * kStgH * 2;   // 73728 B

__global__ __launch_bounds__(256, 2) void gemm_f16(
        const __half* __restrict__ A, const __half* __restrict__ Bw,
        const float* __restrict__ bias, void* __restrict__ Cv,
        int M, int N, int K, int epi,
        const float* __restrict__ res, int gate_off) {
    extern __shared__ __half hsm[];
    __half* As = hsm;                    // [2][128][72]
    __half* Bs = hsm + 2 * kStgH;        // [2][128][72]

    int tid = threadIdx.x;
    int lane = tid & 31;
    int warp = tid >> 5;
    int warp_m = warp & 3;
    int warp_n = warp >> 2;
    int gid = lane >> 2;
    int tig = lane & 3;

    float acc[2][8][4];
    #pragma unroll
    for (int mt = 0; mt < 2; ++mt)
        #pragma unroll
        for (int nt = 0; nt < 8; ++nt)
            #pragma unroll
            for (int i = 0; i < 4; ++i) acc[mt][nt][i] = 0.f;

    const __half* Ag = A + (size_t)(blockIdx.y * 128) * K;
    const __half* Bg = Bw + (size_t)(blockIdx.x * 128) * K;

    uint32_t sA = (uint32_t)__cvta_generic_to_shared(As);
    uint32_t sB = (uint32_t)__cvta_generic_to_shared(Bs);

    int a_row = warp_m * 32 + (lane & 15);
    int a_c8  = (lane >> 4) * 8;
    int b_row = warp_n * 64 + ((lane >> 4) & 1) * 8 + (lane & 7);
    int b_c8  = ((lane >> 3) & 1) * 8;

    auto load_tile = [&](int buf, int kt) {
        #pragma unroll
        for (int p = 0; p < 4; ++p) {
            int idx = tid + p * 256;
            int row = idx >> 3, c16 = idx & 7;
            uint32_t doff = (uint32_t)((buf * kStgH + row * kLSh + c16 * 8) * 2);
            cp16(sA + doff, Ag + (size_t)row * K + kt + c16 * 8);
            cp16(sB + doff, Bg + (size_t)row * K + kt + c16 * 8);
        }
        asm volatile("cp.async.commit_group;" ::: "memory");
    };

    const int T = K / kKT;
    load_tile(0, 0);

    for (int t = 0; t < T; ++t) {
        if (t + 1 < T) {
            load_tile((t + 1) & 1, (t + 1) * kKT);
            asm volatile("cp.async.wait_group 1;" ::: "memory");
        } else {
            asm volatile("cp.async.wait_group 0;" ::: "memory");
        }
        __syncthreads();

        uint32_t aStage = sA + (uint32_t)((t & 1) * kStgH * 2);
        uint32_t bStage = sB + (uint32_t)((t & 1) * kStgH * 2);

        #pragma unroll
        for (int kk = 0; kk < kKT; kk += 16) {
            uint32_t af[2][4];
            #pragma unroll
            for (int mt = 0; mt < 2; ++mt) {
                uint32_t ad = aStage + (uint32_t)(((a_row + mt * 16) * kLSh + kk + a_c8) * 2);
                ldsm_x4(af[mt][0], af[mt][1], af[mt][2], af[mt][3], ad);
            }
            uint32_t bf[8][2];
            #pragma unroll
            for (int nt0 = 0; nt0 < 8; nt0 += 2) {
                uint32_t bd = bStage + (uint32_t)(((b_row + nt0 * 8) * kLSh + kk + b_c8) * 2);
                ldsm_x4(bf[nt0][0], bf[nt0][1], bf[nt0 + 1][0], bf[nt0 + 1][1], bd);
            }
            #pragma unroll
            for (int nt = 0; nt < 8; ++nt)
                #pragma unroll
                for (int mt = 0; mt < 2; ++mt)
                    mma_f16(acc[mt][nt], af[mt][0], af[mt][1], af[mt][2], af[mt][3],
                            bf[nt][0], bf[nt][1]);
        }
        __syncthreads();
    }

    int mode = epi & 7;
    bool out_half = (epi & 16) != 0;
    bool qkv_blk  = (epi & 32) != 0;
    int rbase = blockIdx.y * 128 + warp_m * 32;
    int cbase = blockIdx.x * 128 + warp_n * 64;
    #pragma unroll
    for (int mt = 0; mt < 2; ++mt) {
        #pragma unroll
        for (int half = 0; half < 2; ++half) {
            int r = rbase + mt * 16 + gid + half * 8;
            int b = r >> 10;
            const float* gate = g_ada + b * 6 * kC + gate_off;
            int rout = r;
            if (mode == 3) {
                int win = r >> 6, t = r & 63;
                int nw_ = win & 15;
                int i2 = (nw_ >> 2) * 8 + (t >> 3);
                int j2 = (nw_ & 3) * 8 + (t & 7);
                int ii = (i2 + kSS) & 31, jj = (j2 + kSS) & 31;
                rout = b * kL + ii * 32 + jj;
            }
            #pragma unroll
            for (int nt = 0; nt < 8; ++nt) {
                int c = cbase + nt * 8 + tig * 2;
                float v0 = acc[mt][nt][half * 2 + 0] + bias[c];
                float v1 = acc[mt][nt][half * 2 + 1] + bias[c + 1];
                if (mode == 1) {
                    v0 = gelu_fast(v0);
                    v1 = gelu_fast(v1);
                } else if (mode >= 2) {
                    v0 = res[(size_t)rout * kC + c]     + gate[c]     * v0;
                    v1 = res[(size_t)rout * kC + c + 1] + gate[c + 1] * v1;
                }
                if (qkv_blk) {
                    // head-blocked: [win][part][head][token][32]
                    int win = rout >> 6, tok = rout & 63;
                    int part = c >> 9, rem = c & 511;
                    size_t dst = (size_t)win * 98304 + part * 32768
                               + (rem >> 5) * 2048 + tok * 32 + (rem & 31);
                    *(__half2*)((__half*)Cv + dst) =
                        __float22half2_rn(make_float2(v0, v1));
                } else if (out_half) {
                    *(__half2*)((__half*)Cv + (size_t)rout * N + c) =
                        __float22half2_rn(make_float2(v0, v1));
                } else {
                    *(float2*)((float*)Cv + (size_t)rout * N + c) = make_float2(v0, v1);
                }
            }
        }
    }
}

// ---------------- window attention via FP16 MMA, register softmax ------------
// g_qkv is head-blocked: [win][part][head][token][32]
constexpr int kQSh = 40;
constexpr int kSHh = 72;
__global__ __launch_bounds__(128) void attn_kernel(const float* __restrict__ rpb) {
    int win = blockIdx.x, head = blockIdx.y;
    __shared__ __half qs[64 * kQSh];
    __shared__ __half ks[64 * kQSh];
    __shared__ __half vt[32 * kSHh];
    __shared__ __half sh[64 * kSHh];
    __shared__ int sid[64];
    int tid = threadIdx.x;
    int lane = tid & 31;
    int warp = tid >> 5;
    int gid = lane >> 2;
    int tig = lane & 3;

    const __half* qh = g_qkv + (size_t)win * 98304 + head * 2048;
    const __half* kh = qh + 32768;
    const __half* vh = qh + 65536;
    // q,k: 2048 halves each = 256 x 16B chunks; 2 chunks per thread
    #pragma unroll
    for (int p = 0; p < 2; ++p) {
        int idx = tid + p * 128;
        int n = idx >> 2, c8 = (idx & 3) * 8;
        *(uint4*)(qs + n * kQSh + c8) = *(const uint4*)(qh + idx * 8);
        *(uint4*)(ks + n * kQSh + c8) = *(const uint4*)(kh + idx * 8);
    }
    // v transposed: 1024 half2, 8 per thread
    #pragma unroll
    for (int p = 0; p < 8; ++p) {
        int idx = tid + p * 128;
        int n = idx >> 4, d2 = (idx & 15) * 2;
        __half2 v = *(const __half2*)(vh + n * 32 + d2);
        vt[(d2    ) * kSHh + n] = __low2half(v);
        vt[(d2 + 1) * kSHh + n] = __high2half(v);
    }
    if (tid < 64) {
        int nw_ = win & 15, hb = nw_ >> 2, wb = nw_ & 3;
        int i = hb * 8 + (tid >> 3), j = wb * 8 + (tid & 7);
        int ri = i < 24 ? 0 : (i < 28 ? 1 : 2);
        int rj = j < 24 ? 0 : (j < 28 ? 1 : 2);
        sid[tid] = ri * 3 + rj;
    }
    __syncthreads();

    // ---- S = Q K^T ----
    float c[8][4];
    #pragma unroll
    for (int nt = 0; nt < 8; ++nt)
        #pragma unroll
        for (int i = 0; i < 4; ++i) c[nt][i] = 0.f;

    int m0 = warp * 16 + gid;
    #pragma unroll
    for (int kk = 0; kk < 32; kk += 16) {
        uint32_t a0 = ldsm_u32(qs + (m0    ) * kQSh + kk + 2 * tig);
        uint32_t a1 = ldsm_u32(qs + (m0 + 8) * kQSh + kk + 2 * tig);
        uint32_t a2 = ldsm_u32(qs + (m0    ) * kQSh + kk + 2 * tig + 8);
        uint32_t a3 = ldsm_u32(qs + (m0 + 8) * kQSh + kk + 2 * tig + 8);
        #pragma unroll
        for (int nt = 0; nt < 8; ++nt) {
            int n0 = nt * 8 + gid;
            uint32_t b0 = ldsm_u32(ks + n0 * kQSh + kk + 2 * tig);
            uint32_t b1 = ldsm_u32(ks + n0 * kQSh + kk + 2 * tig + 8);
            mma_f16(c[nt], a0, a1, a2, a3, b0, b1);
        }
    }

    const float scale = 0.17677669529663687f;
    #pragma unroll
    for (int nt = 0; nt < 8; ++nt) {
        #pragma unroll
        for (int idx = 0; idx < 4; ++idx) {
            int row = m0 + ((idx >> 1) << 3);
            int col = nt * 8 + tig * 2 + (idx & 1);
            int di = (row >> 3) - (col >> 3) + 7;
            int dj = (row & 7) - (col & 7) + 7;
            float bias_ = rpb[(di * 15 + dj) * kHeads + head];
            float msk = (sid[row] != sid[col]) ? -100.f : 0.f;
            c[nt][idx] = c[nt][idx] * scale + bias_ + msk;
        }
    }

    // ---- register softmax ----
    #pragma unroll
    for (int half = 0; half < 2; ++half) {
        int row = m0 + half * 8;
        float mx = -1e30f;
        #pragma unroll
        for (int nt = 0; nt < 8; ++nt)
            mx = fmaxf(mx, fmaxf(c[nt][half * 2], c[nt][half * 2 + 1]));
        mx = fmaxf(mx, __shfl_xor_sync(0xffffffffu, mx, 1));
        mx = fmaxf(mx, __shfl_xor_sync(0xffffffffu, mx, 2));
        float sum = 0.f;
        #pragma unroll
        for (int nt = 0; nt < 8; ++nt) {
            float e0 = __expf(c[nt][half * 2    ] - mx);
            float e1 = __expf(c[nt][half * 2 + 1] - mx);
            c[nt][half * 2] = e0;
            c[nt][half * 2 + 1] = e1;
            sum += e0 + e1;
        }
        sum += __shfl_xor_sync(0xffffffffu, sum, 1);
        sum += __shfl_xor_sync(0xffffffffu, sum, 2);
        float inv = __fdividef(1.f, sum);
        #pragma unroll
        for (int nt = 0; nt < 8; ++nt) {
            int col = nt * 8 + tig * 2;
            *(__half2*)(sh + row * kSHh + col) =
                __float22half2_rn(make_float2(c[nt][half * 2] * inv,
                                              c[nt][half * 2 + 1] * inv));
        }
    }
    __syncwarp();

    // ---- O = S V ----
    float o[4][4];
    #pragma unroll
    for (int nt = 0; nt < 4; ++nt)
        #pragma unroll
        for (int i = 0; i < 4; ++i) o[nt][i] = 0.f;

    #pragma unroll
    for (int kk = 0; kk < 64; kk += 16) {
        uint32_t a0 = ldsm_u32(sh + (m0    ) * kSHh + kk + 2 * tig);
        uint32_t a1 = ldsm_u32(sh + (m0 + 8) * kSHh + kk + 2 * tig);
        uint32_t a2 = ldsm_u32(sh + (m0    ) * kSHh + kk + 2 * tig + 8);
        uint32_t a3 = ldsm_u32(sh + (m0 + 8) * kSHh + kk + 2 * tig + 8);
        #pragma unroll
        for (int nt = 0; nt < 4; ++nt) {
            int n0 = nt * 8 + gid;
            uint32_t b0 = ldsm_u32(vt + n0 * kSHh + kk + 2 * tig);
            uint32_t b1 = ldsm_u32(vt + n0 * kSHh + kk + 2 * tig + 8);
            mma_f16(o[nt], a0, a1, a2, a3, b0, b1);
        }
    }

    __half* outp = g_attn + (size_t)win * 64 * kC + head * 32;
    #pragma unroll
    for (int half = 0; half < 2; ++half) {
        int row = m0 + half * 8;
        #pragma unroll
        for (int nt = 0; nt < 4; ++nt) {
            int col = nt * 8 + tig * 2;
            *(__half2*)(outp + (size_t)row * kC + col) =
                __float22half2_rn(make_float2(o[nt][half * 2], o[nt][half * 2 + 1]));
        }
    }
}

// ---------------- launch ----------------
extern "C" void kernel_launch(void* const* d_in, const int* in_sizes, int n_in,
                              void* d_out, int out_size) {
    const float* x       = (const float*)d_in[0];
    const float* cond    = (const float*)d_in[1];
    const float* norm1_w = (const float*)d_in[2];
    const float* norm1_b = (const float*)d_in[3];
    const float* qkv_w   = (const float*)d_in[4];
    const float* qkv_b   = (const float*)d_in[5];
    const float* rpb     = (const float*)d_in[6];
    const float* proj_w  = (const float*)d_in[7];
    const float* proj_b  = (const float*)d_in[8];
    const float* norm2_w = (const float*)d_in[9];
    const float* norm2_b = (const float*)d_in[10];
    const float* fc1_w   = (const float*)d_in[11];
    const float* fc1_b   = (const float*)d_in[12];
    const float* fc2_w   = (const float*)d_in[13];
    const float* fc2_b   = (const float*)d_in[14];
    const float* ada_w   = (const float*)d_in[15];
    const float* ada_b   = (const float*)d_in[16];
    float* out = (float*)d_out;

    void *p_hw, *p_qkv, *p_attn, *p_x2, *p_m, *p_fc1;
    void *p_wq, *p_wp, *p_w1, *p_w2;
    cudaGetSymbolAddress(&p_hw,   g_hw);
    cudaGetSymbolAddress(&p_qkv,  g_qkv);
    cudaGetSymbolAddress(&p_attn, g_attn);
    cudaGetSymbolAddress(&p_x2,   g_x2);
    cudaGetSymbolAddress(&p_m,    g_m);
    cudaGetSymbolAddress(&p_fc1,  g_fc1);
    cudaGetSymbolAddress(&p_wq,   g_wq);
    cudaGetSymbolAddress(&p_wp,   g_wp);
    cudaGetSymbolAddress(&p_w1,   g_w1);
    cudaGetSymbolAddress(&p_w2,   g_w2);

    static bool attr_set = false;
    if (!attr_set) {
        cudaFuncSetAttribute(gemm_f16, cudaFuncAttributeMaxDynamicSharedMemorySize, kGemmSmem);
        attr_set = true;
    }

    // 1. setup: ada (32 blocks) + weight fp16 convert (3072 blocks)
    setup_kernel<<<32 + 786432 / 256, 256>>>(cond, ada_w, ada_b,
                                             qkv_w, (__half*)p_wq, proj_w, (__half*)p_wp,
                                             fc1_w, (__half*)p_w1, fc2_w, (__half*)p_w2);
    // 2. LN1 + modulate + roll + window partition -> g_hw (fp16)
    ln_mod_kernel<<<kRows, 128>>>(x, norm1_w, norm1_b, (__half*)p_hw, 0, 0, kC);
    // 3. qkv (fp16 out, head-blocked layout)
    gemm_f16<<<dim3(12, 256), 256, kGemmSmem>>>(
        (const __half*)p_hw, (const __half*)p_wq, qkv_b, p_qkv, kRows, 1536, 512, 0 | 32, nullptr, 0);
    // 4. windowed attention -> g_attn (fp16)
    attn_kernel<<<dim3(kB * kNW, kHeads), 128>>>(rpb);
    // 5. proj GEMM + window-reverse + MSA residual -> g_x2 (fp32)
    gemm_f16<<<dim3(4, 256), 256, kGemmSmem>>>(
        (const __half*)p_attn, (const __half*)p_wp, proj_b, p_x2, kRows, 512, 512, 3, x, 2 * kC);
    // 6. LN2 + modulate -> g_m (fp16)
    ln_mod_kernel<<<kRows, 128>>>((const float*)p_x2, norm2_w, norm2_b, (__half*)p_m,
                                  1, 3 * kC, 4 * kC);
    // 7. fc1 + GELU -> g_fc1 (fp16)
    gemm_f16<<<dim3(16, 256), 256, kGemmSmem>>>(
        (const __half*)p_m, (const __half*)p_w1, fc1_b, p_fc1, kRows, 2048, 512, 1 | 16, nullptr, 0);
    // 8. fc2 + gated residual -> d_out (fp32)
    gemm_f16<<<dim3(4, 256), 256, kGemmSmem>>>(
        (const __half*)p_fc1, (const __half*)p_w2, fc2_b, out, kRows, 512, 2048, 2, (const float*)p_x2, 5 * kC);
}

// round 17
// speedup vs baseline: 1.2320x; 1.1185x over previous
#include <cuda_runtime.h>
#include <cuda_fp16.h>
#include <math.h>
#include <stdint.h>

// ---------------- problem constants ----------------
constexpr int kB = 32;
constexpr int kC = 512;
constexpr int kHeads = 16;
constexpr int kSS = 4;
constexpr int kNW = 16;
constexpr int kL = 1024;
constexpr int kRows = kB * kL;    // 32768

// ---------------- scratch ----------------
__device__ __align__(16) float  g_ada[kB * 6 * kC];
__device__ __align__(16) __half g_hw[(size_t)kRows * kC];
__device__ __align__(16) __half g_qkv[(size_t)kRows * 3 * kC];   // head-blocked layout
__device__ __align__(16) __half g_attn[(size_t)kRows * kC];
__device__ __align__(16) __half g_x2[(size_t)kRows * kC];        // residual stream (fp16)
__device__ __align__(16) __half g_m[(size_t)kRows * kC];
__device__ __align__(16) __half g_fc1[(size_t)kRows * 4 * kC];
// FP16 weight copies
__device__ __align__(16) __half g_wq[1536 * 512];
__device__ __align__(16) __half g_wp[512 * 512];
__device__ __align__(16) __half g_w1[2048 * 512];
__device__ __align__(16) __half g_w2[512 * 2048];

__device__ __forceinline__ void cp16(uint32_t dst_smem, const void* src) {
    asm volatile("cp.async.cg.shared.global [%0], [%1], 16;" :: "r"(dst_smem), "l"(src));
}
__device__ __forceinline__ void mma_f16(float* c, uint32_t a0, uint32_t a1, uint32_t a2,
                                        uint32_t a3, uint32_t b0, uint32_t b1) {
    asm volatile(
        "mma.sync.aligned.m16n8k16.row.col.f32.f16.f16.f32 "
        "{%0,%1,%2,%3}, {%4,%5,%6,%7}, {%8,%9}, {%0,%1,%2,%3};"
        : "+f"(c[0]), "+f"(c[1]), "+f"(c[2]), "+f"(c[3])
        : "r"(a0), "r"(a1), "r"(a2), "r"(a3), "r"(b0), "r"(b1));
}
__device__ __forceinline__ void ldsm_x4(uint32_t& r0, uint32_t& r1, uint32_t& r2,
                                        uint32_t& r3, uint32_t addr) {
    asm volatile("ldmatrix.sync.aligned.m8n8.x4.shared.b16 {%0,%1,%2,%3}, [%4];"
                 : "=r"(r0), "=r"(r1), "=r"(r2), "=r"(r3) : "r"(addr));
}
__device__ __forceinline__ uint32_t ldsm_u32(const __half* p) {
    return *(const uint32_t*)p;
}

// Fast exact-GELU: A&S 7.1.26 erf (abs err <= 1.5e-7), MUFU rcp + MUFU exp.
__device__ __forceinline__ float gelu_fast(float x) {
    float z = fabsf(x) * 0.70710678118654752f;
    float t = __fdividef(1.f, 1.f + 0.3275911f * z);
    float poly = ((((1.061405429f * t - 1.453152027f) * t + 1.421413741f) * t
                   - 0.284496736f) * t + 0.254829592f) * t;
    float erfa = 1.f - poly * __expf(-z * z);
    float erfv = (x >= 0.f) ? erfa : -erfa;
    return 0.5f * x * (1.f + erfv);
}

// ---------------- fused setup: ada (blocks 0..31, warp-coop) + weight cvt ----
__global__ void setup_kernel(const float* __restrict__ cond,
                             const float* __restrict__ ada_w,
                             const float* __restrict__ ada_b,
                             const float* __restrict__ s0, __half* __restrict__ d0,
                             const float* __restrict__ s1, __half* __restrict__ d1,
                             const float* __restrict__ s2, __half* __restrict__ d2,
                             const float* __restrict__ s3, __half* __restrict__ d3) {
    if (blockIdx.x < 32) {
        int b = blockIdx.x;
        __shared__ float sc[kC];
        for (int i = threadIdx.x; i < kC; i += blockDim.x) {
            float c = cond[b * kC + i];
            sc[i] = c / (1.f + __expf(-c));
        }
        __syncthreads();
        int warp = threadIdx.x >> 5, lane = threadIdx.x & 31;
        for (int n = warp; n < 6 * kC; n += 8) {
            const float* wr = ada_w + (size_t)n * kC;
            float acc = 0.f;
            #pragma unroll
            for (int k = lane; k < kC; k += 32) acc += sc[k] * wr[k];
            #pragma unroll
            for (int o = 16; o; o >>= 1) acc += __shfl_down_sync(0xffffffffu, acc, o);
            if (lane == 0) g_ada[b * 6 * kC + n] = acc + ada_b[n];
        }
        return;
    }
    int i = (blockIdx.x - 32) * blockDim.x + threadIdx.x;
    const float* s; __half* d;
    if (i < 196608)      { s = s0; d = d0; }
    else if (i < 262144) { s = s1; d = d1; i -= 196608; }
    else if (i < 524288) { s = s2; d = d2; i -= 262144; }
    else                 { s = s3; d = d3; i -= 524288; }
    float4 v = ((const float4*)s)[i];
    __half2* dp = (__half2*)(d + (size_t)i * 4);
    dp[0] = __float22half2_rn(make_float2(v.x, v.y));
    dp[1] = __float22half2_rn(make_float2(v.z, v.w));
}

// ---------------- LN + modulate (+ roll/partition gather); fp16 out ----------
// in_half: input rows are fp16 (residual stream) instead of fp32.
__global__ void ln_mod_kernel(const void* __restrict__ xin,
                              const float* __restrict__ lnw,
                              const float* __restrict__ lnb,
                              __half* __restrict__ out,
                              int mode, int sh_off, int sc_off, int in_half) {
    int r = blockIdx.x;
    int b, src;
    if (mode == 0) {
        int win = r >> 6, t = r & 63;
        b = win >> 4;
        int nw_ = win & 15;
        int hb = nw_ >> 2, wb = nw_ & 3;
        int i = hb * 8 + (t >> 3), j = wb * 8 + (t & 7);
        int si = (i + kSS) & 31, sj = (j + kSS) & 31;
        src = b * kL + si * 32 + sj;
    } else {
        b = r >> 10;
        src = r;
    }
    int tid = threadIdx.x;
    float4 v;
    if (in_half) {
        const __half2* xp = (const __half2*)((const __half*)xin + (size_t)src * kC);
        __half2 h0 = xp[tid * 2], h1 = xp[tid * 2 + 1];
        v = make_float4(__low2float(h0), __high2float(h0),
                        __low2float(h1), __high2float(h1));
    } else {
        v = ((const float4*)((const float*)xin + (size_t)src * kC))[tid];
    }
    float s = v.x + v.y + v.z + v.w;
    float ss = v.x * v.x + v.y * v.y + v.z * v.z + v.w * v.w;
    #pragma unroll
    for (int o = 16; o; o >>= 1) {
        s  += __shfl_down_sync(0xffffffffu, s, o);
        ss += __shfl_down_sync(0xffffffffu, ss, o);
    }
    __shared__ float ps[4], pss[4], mv[2];
    int wp = tid >> 5;
    if ((tid & 31) == 0) { ps[wp] = s; pss[wp] = ss; }
    __syncthreads();
    if (tid == 0) {
        float S = ps[0] + ps[1] + ps[2] + ps[3];
        float S2 = pss[0] + pss[1] + pss[2] + pss[3];
        float mu = S / kC;
        float var = S2 / kC - mu * mu;
        mv[0] = mu;
        mv[1] = rsqrtf(var + 1e-5f);
    }
    __syncthreads();
    float mu = mv[0], rs = mv[1];
    int c0 = tid * 4;
    const float* sh = g_ada + b * 6 * kC + sh_off;
    const float* sc = g_ada + b * 6 * kC + sc_off;
    float vv[4] = {v.x, v.y, v.z, v.w};
    float o4[4];
    #pragma unroll
    for (int u = 0; u < 4; ++u) {
        float val = (vv[u] - mu) * rs * lnw[c0 + u] + lnb[c0 + u];
        o4[u] = val * (1.f + sc[c0 + u]) + sh[c0 + u];
    }
    __half2* op = (__half2*)(out + (size_t)r * kC + c0);
    op[0] = __float22half2_rn(make_float2(o4[0], o4[1]));
    op[1] = __float22half2_rn(make_float2(o4[2], o4[3]));
}

// ---------------- FP16 mma.sync NT GEMM, 2-stage cp.async, 128x128 block ------
// Warp tile 32x64, 8 warps (4M x 2N), K-tile 64 halves, smem stride 72 halves.
// epi&7: 0 bias. 1 bias+GELU. 2 res+gate*(bias+acc). 3 window-reverse + residual.
// epi&16: fp16 output.  epi&32: head-blocked qkv remap.  epi&64: res is fp16.
constexpr int kKT = 64;
constexpr int kLSh = 72;
constexpr int kStgH = 128 * kLSh;
constexpr int kGemmSmem = 4 * kStgH * 2;   // 73728 B

__global__ __launch_bounds__(256, 2) void gemm_f16(
        const __half* __restrict__ A, const __half* __restrict__ Bw,
        const float* __restrict__ bias, void* __restrict__ Cv,
        int M, int N, int K, int epi,
        const void* __restrict__ res, int gate_off) {
    extern __shared__ __half hsm[];
    __half* As = hsm;                    // [2][128][72]
    __half* Bs = hsm + 2 * kStgH;        // [2][128][72]

    int tid = threadIdx.x;
    int lane = tid & 31;
    int warp = tid >> 5;
    int warp_m = warp & 3;
    int warp_n = warp >> 2;
    int gid = lane >> 2;
    int tig = lane & 3;

    float acc[2][8][4];
    #pragma unroll
    for (int mt = 0; mt < 2; ++mt)
        #pragma unroll
        for (int nt = 0; nt < 8; ++nt)
            #pragma unroll
            for (int i = 0; i < 4; ++i) acc[mt][nt][i] = 0.f;

    const __half* Ag = A + (size_t)(blockIdx.y * 128) * K;
    const __half* Bg = Bw + (size_t)(blockIdx.x * 128) * K;

    uint32_t sA = (uint32_t)__cvta_generic_to_shared(As);
    uint32_t sB = (uint32_t)__cvta_generic_to_shared(Bs);

    int a_row = warp_m * 32 + (lane & 15);
    int a_c8  = (lane >> 4) * 8;
    int b_row = warp_n * 64 + ((lane >> 4) & 1) * 8 + (lane & 7);
    int b_c8  = ((lane >> 3) & 1) * 8;

    auto load_tile = [&](int buf, int kt) {
        #pragma unroll
        for (int p = 0; p < 4; ++p) {
            int idx = tid + p * 256;
            int row = idx >> 3, c16 = idx & 7;
            uint32_t doff = (uint32_t)((buf * kStgH + row * kLSh + c16 * 8) * 2);
            cp16(sA + doff, Ag + (size_t)row * K + kt + c16 * 8);
            cp16(sB + doff, Bg + (size_t)row * K + kt + c16 * 8);
        }
        asm volatile("cp.async.commit_group;" ::: "memory");
    };

    const int T = K / kKT;
    load_tile(0, 0);

    for (int t = 0; t < T; ++t) {
        if (t + 1 < T) {
            load_tile((t + 1) & 1, (t + 1) * kKT);
            asm volatile("cp.async.wait_group 1;" ::: "memory");
        } else {
            asm volatile("cp.async.wait_group 0;" ::: "memory");
        }
        __syncthreads();

        uint32_t aStage = sA + (uint32_t)((t & 1) * kStgH * 2);
        uint32_t bStage = sB + (uint32_t)((t & 1) * kStgH * 2);

        #pragma unroll
        for (int kk = 0; kk < kKT; kk += 16) {
            uint32_t af[2][4];
            #pragma unroll
            for (int mt = 0; mt < 2; ++mt) {
                uint32_t ad = aStage + (uint32_t)(((a_row + mt * 16) * kLSh + kk + a_c8) * 2);
                ldsm_x4(af[mt][0], af[mt][1], af[mt][2], af[mt][3], ad);
            }
            uint32_t bf[8][2];
            #pragma unroll
            for (int nt0 = 0; nt0 < 8; nt0 += 2) {
                uint32_t bd = bStage + (uint32_t)(((b_row + nt0 * 8) * kLSh + kk + b_c8) * 2);
                ldsm_x4(bf[nt0][0], bf[nt0][1], bf[nt0 + 1][0], bf[nt0 + 1][1], bd);
            }
            #pragma unroll
            for (int nt = 0; nt < 8; ++nt)
                #pragma unroll
                for (int mt = 0; mt < 2; ++mt)
                    mma_f16(acc[mt][nt], af[mt][0], af[mt][1], af[mt][2], af[mt][3],
                            bf[nt][0], bf[nt][1]);
        }
        __syncthreads();
    }

    int mode = epi & 7;
    bool out_half = (epi & 16) != 0;
    bool qkv_blk  = (epi & 32) != 0;
    bool res_half = (epi & 64) != 0;
    int rbase = blockIdx.y * 128 + warp_m * 32;
    int cbase = blockIdx.x * 128 + warp_n * 64;
    #pragma unroll
    for (int mt = 0; mt < 2; ++mt) {
        #pragma unroll
        for (int half = 0; half < 2; ++half) {
            int r = rbase + mt * 16 + gid + half * 8;
            int b = r >> 10;
            const float* gate = g_ada + b * 6 * kC + gate_off;
            int rout = r;
            if (mode == 3) {
                int win = r >> 6, t = r & 63;
                int nw_ = win & 15;
                int i2 = (nw_ >> 2) * 8 + (t >> 3);
                int j2 = (nw_ & 3) * 8 + (t & 7);
                int ii = (i2 + kSS) & 31, jj = (j2 + kSS) & 31;
                rout = b * kL + ii * 32 + jj;
            }
            #pragma unroll
            for (int nt = 0; nt < 8; ++nt) {
                int c = cbase + nt * 8 + tig * 2;
                float v0 = acc[mt][nt][half * 2 + 0] + bias[c];
                float v1 = acc[mt][nt][half * 2 + 1] + bias[c + 1];
                if (mode == 1) {
                    v0 = gelu_fast(v0);
                    v1 = gelu_fast(v1);
                } else if (mode >= 2) {
                    float r0, r1;
                    if (res_half) {
                        __half2 h = *(const __half2*)((const __half*)res
                                                      + (size_t)rout * kC + c);
                        r0 = __low2float(h); r1 = __high2float(h);
                    } else {
                        float2 f = *(const float2*)((const float*)res
                                                    + (size_t)rout * kC + c);
                        r0 = f.x; r1 = f.y;
                    }
                    v0 = r0 + gate[c]     * v0;
                    v1 = r1 + gate[c + 1] * v1;
                }
                if (qkv_blk) {
                    int win = rout >> 6, tok = rout & 63;
                    int part = c >> 9, rem = c & 511;
                    size_t dst = (size_t)win * 98304 + part * 32768
                               + (rem >> 5) * 2048 + tok * 32 + (rem & 31);
                    *(__half2*)((__half*)Cv + dst) =
                        __float22half2_rn(make_float2(v0, v1));
                } else if (out_half) {
                    *(__half2*)((__half*)Cv + (size_t)rout * N + c) =
                        __float22half2_rn(make_float2(v0, v1));
                } else {
                    *(float2*)((float*)Cv + (size_t)rout * N + c) = make_float2(v0, v1);
                }
            }
        }
    }
}

// ---------------- window attention via FP16 MMA, register softmax ------------
// g_qkv is head-blocked: [win][part][head][token][32]
constexpr int kQSh = 40;
constexpr int kSHh = 72;
__global__ __launch_bounds__(128) void attn_kernel(const float* __restrict__ rpb) {
    int win = blockIdx.x, head = blockIdx.y;
    __shared__ __half qs[64 * kQSh];
    __shared__ __half ks[64 * kQSh];
    __shared__ __half vt[32 * kSHh];
    __shared__ __half sh[64 * kSHh];
    __shared__ int sid[64];
    int tid = threadIdx.x;
    int lane = tid & 31;
    int warp = tid >> 5;
    int gid = lane >> 2;
    int tig = lane & 3;

    const __half* qh = g_qkv + (size_t)win * 98304 + head * 2048;
    const __half* kh = qh + 32768;
    const __half* vh = qh + 65536;
    #pragma unroll
    for (int p = 0; p < 2; ++p) {
        int idx = tid + p * 128;
        int n = idx >> 2, c8 = (idx & 3) * 8;
        *(uint4*)(qs + n * kQSh + c8) = *(const uint4*)(qh + idx * 8);
        *(uint4*)(ks + n * kQSh + c8) = *(const uint4*)(kh + idx * 8);
    }
    #pragma unroll
    for (int p = 0; p < 8; ++p) {
        int idx = tid + p * 128;
        int n = idx >> 4, d2 = (idx & 15) * 2;
        __half2 v = *(const __half2*)(vh + n * 32 + d2);
        vt[(d2    ) * kSHh + n] = __low2half(v);
        vt[(d2 + 1) * kSHh + n] = __high2half(v);
    }
    if (tid < 64) {
        int nw_ = win & 15, hb = nw_ >> 2, wb = nw_ & 3;
        int i = hb * 8 + (tid >> 3), j = wb * 8 + (tid & 7);
        int ri = i < 24 ? 0 : (i < 28 ? 1 : 2);
        int rj = j < 24 ? 0 : (j < 28 ? 1 : 2);
        sid[tid] = ri * 3 + rj;
    }
    __syncthreads();

    float c[8][4];
    #pragma unroll
    for (int nt = 0; nt < 8; ++nt)
        #pragma unroll
        for (int i = 0; i < 4; ++i) c[nt][i] = 0.f;

    int m0 = warp * 16 + gid;
    #pragma unroll
    for (int kk = 0; kk < 32; kk += 16) {
        uint32_t a0 = ldsm_u32(qs + (m0    ) * kQSh + kk + 2 * tig);
        uint32_t a1 = ldsm_u32(qs + (m0 + 8) * kQSh + kk + 2 * tig);
        uint32_t a2 = ldsm_u32(qs + (m0    ) * kQSh + kk + 2 * tig + 8);
        uint32_t a3 = ldsm_u32(qs + (m0 + 8) * kQSh + kk + 2 * tig + 8);
        #pragma unroll
        for (int nt = 0; nt < 8; ++nt) {
            int n0 = nt * 8 + gid;
            uint32_t b0 = ldsm_u32(ks + n0 * kQSh + kk + 2 * tig);
            uint32_t b1 = ldsm_u32(ks + n0 * kQSh + kk + 2 * tig + 8);
            mma_f16(c[nt], a0, a1, a2, a3, b0, b1);
        }
    }

    const float scale = 0.17677669529663687f;
    #pragma unroll
    for (int nt = 0; nt < 8; ++nt) {
        #pragma unroll
        for (int idx = 0; idx < 4; ++idx) {
            int row = m0 + ((idx >> 1) << 3);
            int col = nt * 8 + tig * 2 + (idx & 1);
            int di = (row >> 3) - (col >> 3) + 7;
            int dj = (row & 7) - (col & 7) + 7;
            float bias_ = rpb[(di * 15 + dj) * kHeads + head];
            float msk = (sid[row] != sid[col]) ? -100.f : 0.f;
            c[nt][idx] = c[nt][idx] * scale + bias_ + msk;
        }
    }

    #pragma unroll
    for (int half = 0; half < 2; ++half) {
        int row = m0 + half * 8;
        float mx = -1e30f;
        #pragma unroll
        for (int nt = 0; nt < 8; ++nt)
            mx = fmaxf(mx, fmaxf(c[nt][half * 2], c[nt][half * 2 + 1]));
        mx = fmaxf(mx, __shfl_xor_sync(0xffffffffu, mx, 1));
        mx = fmaxf(mx, __shfl_xor_sync(0xffffffffu, mx, 2));
        float sum = 0.f;
        #pragma unroll
        for (int nt = 0; nt < 8; ++nt) {
            float e0 = __expf(c[nt][half * 2    ] - mx);
            float e1 = __expf(c[nt][half * 2 + 1] - mx);
            c[nt][half * 2] = e0;
            c[nt][half * 2 + 1] = e1;
            sum += e0 + e1;
        }
        sum += __shfl_xor_sync(0xffffffffu, sum, 1);
        sum += __shfl_xor_sync(0xffffffffu, sum, 2);
        float inv = __fdividef(1.f, sum);
        #pragma unroll
        for (int nt = 0; nt < 8; ++nt) {
            int col = nt * 8 + tig * 2;
            *(__half2*)(sh + row * kSHh + col) =
                __float22half2_rn(make_float2(c[nt][half * 2] * inv,
                                              c[nt][half * 2 + 1] * inv));
        }
    }
    __syncwarp();

    float o[4][4];
    #pragma unroll
    for (int nt = 0; nt < 4; ++nt)
        #pragma unroll
        for (int i = 0; i < 4; ++i) o[nt][i] = 0.f;

    #pragma unroll
    for (int kk = 0; kk < 64; kk += 16) {
        uint32_t a0 = ldsm_u32(sh + (m0    ) * kSHh + kk + 2 * tig);
        uint32_t a1 = ldsm_u32(sh + (m0 + 8) * kSHh + kk + 2 * tig);
        uint32_t a2 = ldsm_u32(sh + (m0    ) * kSHh + kk + 2 * tig + 8);
        uint32_t a3 = ldsm_u32(sh + (m0 + 8) * kSHh + kk + 2 * tig + 8);
        #pragma unroll
        for (int nt = 0; nt < 4; ++nt) {
            int n0 = nt * 8 + gid;
            uint32_t b0 = ldsm_u32(vt + n0 * kSHh + kk + 2 * tig);
            uint32_t b1 = ldsm_u32(vt + n0 * kSHh + kk + 2 * tig + 8);
            mma_f16(o[nt], a0, a1, a2, a3, b0, b1);
        }
    }

    __half* outp = g_attn + (size_t)win * 64 * kC + head * 32;
    #pragma unroll
    for (int half = 0; half < 2; ++half) {
        int row = m0 + half * 8;
        #pragma unroll
        for (int nt = 0; nt < 4; ++nt) {
            int col = nt * 8 + tig * 2;
            *(__half2*)(outp + (size_t)row * kC + col) =
                __float22half2_rn(make_float2(o[nt][half * 2], o[nt][half * 2 + 1]));
        }
    }
}

// ---------------- launch ----------------
extern "C" void kernel_launch(void* const* d_in, const int* in_sizes, int n_in,
                              void* d_out, int out_size) {
    const float* x       = (const float*)d_in[0];
    const float* cond    = (const float*)d_in[1];
    const float* norm1_w = (const float*)d_in[2];
    const float* norm1_b = (const float*)d_in[3];
    const float* qkv_w   = (const float*)d_in[4];
    const float* qkv_b   = (const float*)d_in[5];
    const float* rpb     = (const float*)d_in[6];
    const float* proj_w  = (const float*)d_in[7];
    const float* proj_b  = (const float*)d_in[8];
    const float* norm2_w = (const float*)d_in[9];
    const float* norm2_b = (const float*)d_in[10];
    const float* fc1_w   = (const float*)d_in[11];
    const float* fc1_b   = (const float*)d_in[12];
    const float* fc2_w   = (const float*)d_in[13];
    const float* fc2_b   = (const float*)d_in[14];
    const float* ada_w   = (const float*)d_in[15];
    const float* ada_b   = (const float*)d_in[16];
    float* out = (float*)d_out;

    void *p_hw, *p_qkv, *p_attn, *p_x2, *p_m, *p_fc1;
    void *p_wq, *p_wp, *p_w1, *p_w2;
    cudaGetSymbolAddress(&p_hw,   g_hw);
    cudaGetSymbolAddress(&p_qkv,  g_qkv);
    cudaGetSymbolAddress(&p_attn, g_attn);
    cudaGetSymbolAddress(&p_x2,   g_x2);
    cudaGetSymbolAddress(&p_m,    g_m);
    cudaGetSymbolAddress(&p_fc1,  g_fc1);
    cudaGetSymbolAddress(&p_wq,   g_wq);
    cudaGetSymbolAddress(&p_wp,   g_wp);
    cudaGetSymbolAddress(&p_w1,   g_w1);
    cudaGetSymbolAddress(&p_w2,   g_w2);

    static bool attr_set = false;
    if (!attr_set) {
        cudaFuncSetAttribute(gemm_f16, cudaFuncAttributeMaxDynamicSharedMemorySize, kGemmSmem);
        attr_set = true;
    }

    // 1. setup: ada (32 blocks, warp-coop) + weight fp16 convert (3072 blocks)
    setup_kernel<<<32 + 786432 / 256, 256>>>(cond, ada_w, ada_b,
                                             qkv_w, (__half*)p_wq, proj_w, (__half*)p_wp,
                                             fc1_w, (__half*)p_w1, fc2_w, (__half*)p_w2);
    // 2. LN1 + modulate + roll + window partition -> g_hw (fp16)
    ln_mod_kernel<<<kRows, 128>>>(x, norm1_w, norm1_b, (__half*)p_hw, 0, 0, kC, 0);
    // 3. qkv (fp16 out, head-blocked layout)
    gemm_f16<<<dim3(12, 256), 256, kGemmSmem>>>(
        (const __half*)p_hw, (const __half*)p_wq, qkv_b, p_qkv, kRows, 1536, 512, 0 | 32, nullptr, 0);
    // 4. windowed attention -> g_attn (fp16)
    attn_kernel<<<dim3(kB * kNW, kHeads), 128>>>(rpb);
    // 5. proj GEMM + window-reverse + MSA residual -> g_x2 (fp16)
    gemm_f16<<<dim3(4, 256), 256, kGemmSmem>>>(
        (const __half*)p_attn, (const __half*)p_wp, proj_b, p_x2, kRows, 512, 512, 3 | 16, x, 2 * kC);
    // 6. LN2 + modulate -> g_m (fp16, reads fp16 residual)
    ln_mod_kernel<<<kRows, 128>>>(p_x2, norm2_w, norm2_b, (__half*)p_m,
                                  1, 3 * kC, 4 * kC, 1);
    // 7. fc1 + GELU -> g_fc1 (fp16)
    gemm_f16<<<dim3(16, 256), 256, kGemmSmem>>>(
        (const __half*)p_m, (const __half*)p_w1, fc1_b, p_fc1, kRows, 2048, 512, 1 | 16, nullptr, 0);
    // 8. fc2 + gated residual (fp16 res) -> d_out (fp32)
    gemm_f16<<<dim3(4, 256), 256, kGemmSmem>>>(
        (const __half*)p_fc1, (const __half*)p_w2, fc2_b, out, kRows, 512, 2048, 2 | 64, p_x2, 5 * kC);
}